// round 5
// baseline (speedup 1.0000x reference)
#include <cuda_runtime.h>
#include <cuda_bf16.h>

#define NN  16384
#define DD  32
#define INPD 256
#define UU  128
#define RR  8
#define ENTT 8

// ---------------- scratch (device globals: no allocation allowed) ----------------
__device__ float g_center[NN * UU];            // (N, U)
__device__ float g_qr[NN * RR * UU];           // (N, R*U)  per-node per-relation query
__device__ float g_s[NN * RR * UU];            // (N, R*U)  attn-weighted neighbor sums
__device__ float g_kT[UU * UU];                // k_w^T
__device__ float g_relT[RR * UU * UU];         // rel_w[r]^T
__device__ float g_qk[UU * UU];                // q_w @ k_w^T
__device__ float g_vf[UU * UU];                // v_w @ fc_w
__device__ float g_Bk2[UU * RR * UU];          // (U, R*U): col r*128+a = (1/U) * qk @ rel_w[r]^T
__device__ float g_Bv2[RR * UU * UU];          // (R*U, U): rel_w[r] @ vf
__device__ int   g_cnt[ENTT];
__device__ int   g_lists[ENTT * NN];

// ---------------- transpose k_w and rel_w[r] ----------------
__global__ void transpose_kernel(const float* __restrict__ k_w,
                                 const float* __restrict__ rel_w)
{
    int m = blockIdx.z;
    const float* src = (m == 0) ? k_w : (rel_w + (m - 1) * UU * UU);
    float* dst = (m == 0) ? g_kT : (g_relT + (m - 1) * UU * UU);
    __shared__ float t[32][33];
    int tx = threadIdx.x, ty = threadIdx.y;   // block (32, 8)
    int x = blockIdx.x * 32 + tx;
    int y0 = blockIdx.y * 32;
#pragma unroll
    for (int i = 0; i < 4; i++)
        t[ty + 8 * i][tx] = src[(y0 + ty + 8 * i) * UU + x];
    __syncthreads();
    int x2 = blockIdx.y * 32 + tx;
    int y2 = blockIdx.x * 32;
#pragma unroll
    for (int i = 0; i < 4; i++)
        dst[(y2 + ty + 8 * i) * UU + x2] = t[tx][ty + 8 * i];
}

// ---------------- entity partition ----------------
__global__ void zero_cnt_kernel() {
    if (threadIdx.x < ENTT) g_cnt[threadIdx.x] = 0;
}
__global__ void partition_kernel(const int* __restrict__ pe) {
    int n = blockIdx.x * blockDim.x + threadIdx.x;
    if (n < NN) {
        int e = pe[n];
        int pos = atomicAdd(&g_cnt[e], 1);
        g_lists[e * NN + pos] = n;
    }
}

// ---------------- generic 64x128x32 tiled fp32 GEMM ----------------
// C[row, n0+col] = alpha * sum_k A[row, k] * B[k, n0+col] (+bias, relu, +addsrc)
// Optional row gather via rowlists/cnts (per blockIdx.z).
__global__ __launch_bounds__(256) void gemm_tile(
    const float* __restrict__ A, int lda, long sAz,
    const float* __restrict__ B, int ldb, long sBz,
    float* __restrict__ C, int ldc, long sCz,
    int M, int K,
    const int* __restrict__ rowlists, const int* __restrict__ cnts,
    const float* __restrict__ bias, const float* __restrict__ addsrc,
    int do_relu, float alpha)
{
    __shared__ float As[64][33];
    __shared__ float Bs[32][128];
    __shared__ int rowidx[64];

    int z = blockIdx.z;
    A += z * sAz; B += z * sBz; C += z * sCz;
    int m0 = blockIdx.x * 64;
    int n0 = blockIdx.y * 128;
    int rows = rowlists ? cnts[z] : M;
    if (m0 >= rows) return;
    const int* rl = rowlists ? (rowlists + z * NN) : nullptr;

    int tid = threadIdx.x;
    if (tid < 64) {
        int g = m0 + tid;
        rowidx[tid] = (g < rows) ? (rl ? rl[g] : g) : -1;
    }
    __syncthreads();

    int tx = tid & 15, ty = tid >> 4;
    float acc[4][8];
#pragma unroll
    for (int i = 0; i < 4; i++)
#pragma unroll
        for (int j = 0; j < 8; j++) acc[i][j] = 0.f;

    for (int kt = 0; kt < K; kt += 32) {
#pragma unroll
        for (int j = 0; j < 8; j++) {          // A: 64x32
            int lin = tid + j * 256;
            int lr = lin >> 5, lc = lin & 31;
            int ar = rowidx[lr];
            As[lr][lc] = (ar >= 0) ? A[ar * lda + kt + lc] : 0.f;
        }
#pragma unroll
        for (int j = 0; j < 16; j++) {         // B: 32x128
            int lin = tid + j * 256;
            int br = lin >> 7, bc = lin & 127;
            Bs[br][bc] = B[(kt + br) * ldb + n0 + bc];
        }
        __syncthreads();
#pragma unroll
        for (int kk = 0; kk < 32; kk++) {
            float bv[8];
#pragma unroll
            for (int j = 0; j < 8; j++) bv[j] = Bs[kk][tx + 16 * j];
#pragma unroll
            for (int i = 0; i < 4; i++) {
                float av = As[ty * 4 + i][kk];
#pragma unroll
                for (int j = 0; j < 8; j++) acc[i][j] += av * bv[j];
            }
        }
        __syncthreads();
    }

#pragma unroll
    for (int i = 0; i < 4; i++) {
        int cr = rowidx[ty * 4 + i];
        if (cr < 0) continue;
#pragma unroll
        for (int j = 0; j < 8; j++) {
            int col = n0 + tx + 16 * j;
            float v = acc[i][j] * alpha;
            if (bias) v += bias[col];
            if (do_relu) v = fmaxf(v, 0.f);
            if (addsrc) v += addsrc[cr * ldc + col];
            C[cr * ldc + col] = v;
        }
    }
}

// ---------------- fused gather / score / softmax / weighted-scatter ----------------
__global__ __launch_bounds__(128) void edge_kernel(const int* __restrict__ adjacency,
                                                   const int* __restrict__ relation)
{
    __shared__ float xs[DD][UU];      // gathered neighbor embeddings
    __shared__ float aw[RR][DD];      // per-relation masked attention
    __shared__ float scores[DD];
    __shared__ int adjs[DD];
    __shared__ int rels[DD];

    int n = blockIdx.x;
    int tid = threadIdx.x, lane = tid & 31, w = tid >> 5;

    if (tid < DD) {
        adjs[tid] = adjacency[n * DD + tid];
        rels[tid] = relation[n * DD + tid];
    }
    __syncthreads();

    // gather x: warp w loads rows d = w*8 .. w*8+7 (float4, coalesced)
#pragma unroll
    for (int i = 0; i < 8; i++) {
        int d = w * 8 + i;
        int idx = adjs[d];
        float4 v = (idx > 0)
            ? reinterpret_cast<const float4*>(g_center + (idx - 1) * UU)[lane]
            : make_float4(0.f, 0.f, 0.f, 0.f);
        reinterpret_cast<float4*>(&xs[d][0])[lane] = v;
    }
    __syncwarp();

    // scores[d] = qr[n, rel[d]] . x[d]  (1/U already folded into g_Bk2)
    const float* qbase = g_qr + n * (RR * UU);
#pragma unroll
    for (int i = 0; i < 8; i++) {
        int d = w * 8 + i;
        int r = rels[d];
        const float* q = qbase + r * UU;
        float s = 0.f;
#pragma unroll
        for (int k2 = 0; k2 < 4; k2++) {
            int c = lane + 32 * k2;
            s += q[c] * xs[d][c];
        }
#pragma unroll
        for (int off = 16; off > 0; off >>= 1) s += __shfl_xor_sync(0xffffffffu, s, off);
        if (lane == 0) scores[d] = (r == 0) ? -1e9f : s;
    }
    __syncthreads();

    // softmax over D=32 (warp 0), then per-relation masked attention
    if (w == 0) {
        float v = scores[lane];
        float m = v;
#pragma unroll
        for (int off = 16; off > 0; off >>= 1) m = fmaxf(m, __shfl_xor_sync(0xffffffffu, m, off));
        float e = __expf(v - m);
        float sum = e;
#pragma unroll
        for (int off = 16; off > 0; off >>= 1) sum += __shfl_xor_sync(0xffffffffu, sum, off);
        float a = e / sum;
        int r = rels[lane];
#pragma unroll
        for (int rr = 0; rr < RR; rr++) aw[rr][lane] = (r == rr) ? a : 0.f;
    }
    __syncthreads();

    // s[n, r, :] = sum_d aw[r][d] * x[d, :]
    float acc[RR];
#pragma unroll
    for (int r = 0; r < RR; r++) acc[r] = 0.f;
#pragma unroll
    for (int d = 0; d < DD; d++) {
        float x = xs[d][tid];
#pragma unroll
        for (int r = 0; r < RR; r++) acc[r] += aw[r][d] * x;
    }
    float* sp = g_s + n * (RR * UU) + tid;
#pragma unroll
    for (int r = 0; r < RR; r++) sp[r * UU] = acc[r];
}

// ---------------- launch ----------------
extern "C" void kernel_launch(void* const* d_in, const int* in_sizes, int n_in,
                              void* d_out, int out_size)
{
    const float* node_state = (const float*)d_in[0];
    const int*   adjacency  = (const int*)d_in[1];
    const int*   point_enc  = (const int*)d_in[2];
    const int*   relation   = (const int*)d_in[3];
    const float* pe_w       = (const float*)d_in[4];
    const float* rel_w      = (const float*)d_in[5];
    const float* q_w        = (const float*)d_in[6];
    const float* k_w        = (const float*)d_in[7];
    const float* v_w        = (const float*)d_in[8];
    const float* fc_w       = (const float*)d_in[9];
    const float* fc_b       = (const float*)d_in[10];
    float* out = (float*)d_out;

    float *p_center, *p_qr, *p_s, *p_kT, *p_relT, *p_qk, *p_vf, *p_Bk2, *p_Bv2;
    int *p_cnt, *p_lists;
    cudaGetSymbolAddress((void**)&p_center, g_center);
    cudaGetSymbolAddress((void**)&p_qr,     g_qr);
    cudaGetSymbolAddress((void**)&p_s,      g_s);
    cudaGetSymbolAddress((void**)&p_kT,     g_kT);
    cudaGetSymbolAddress((void**)&p_relT,   g_relT);
    cudaGetSymbolAddress((void**)&p_qk,     g_qk);
    cudaGetSymbolAddress((void**)&p_vf,     g_vf);
    cudaGetSymbolAddress((void**)&p_Bk2,    g_Bk2);
    cudaGetSymbolAddress((void**)&p_Bv2,    g_Bv2);
    cudaGetSymbolAddress((void**)&p_cnt,    g_cnt);
    cudaGetSymbolAddress((void**)&p_lists,  g_lists);

    // 1. transposes of k_w and rel_w[r]
    transpose_kernel<<<dim3(4, 4, 9), dim3(32, 8)>>>(k_w, rel_w);

    // 2. qk = q_w @ k_w^T ; vf = v_w @ fc_w
    gemm_tile<<<dim3(2, 1, 1), 256>>>(q_w, 128, 0, p_kT, 128, 0, p_qk, 128, 0,
                                      128, 128, nullptr, nullptr, nullptr, nullptr, 0, 1.f);
    gemm_tile<<<dim3(2, 1, 1), 256>>>(v_w, 128, 0, fc_w, 128, 0, p_vf, 128, 0,
                                      128, 128, nullptr, nullptr, nullptr, nullptr, 0, 1.f);

    // 3. Bk2[:, r*128+a] = (1/U) * qk @ rel_w[r]^T ; Bv2[r*128+a, :] = rel_w[r] @ vf
    gemm_tile<<<dim3(2, 1, 8), 256>>>(p_qk, 128, 0, p_relT, 128, (long)UU * UU,
                                      p_Bk2, 1024, 128,
                                      128, 128, nullptr, nullptr, nullptr, nullptr, 0, 1.f / 128.f);
    gemm_tile<<<dim3(2, 1, 8), 256>>>(rel_w, 128, (long)UU * UU, p_vf, 128, 0,
                                      p_Bv2, 128, (long)UU * UU,
                                      128, 128, nullptr, nullptr, nullptr, nullptr, 0, 1.f);

    // 4. entity partition
    zero_cnt_kernel<<<1, 32>>>();
    partition_kernel<<<NN / 256, 256>>>(point_enc);

    // 5. center[n] = node_state[n] @ point_enc_w[point_enc[n]]   (gathered GEMM per entity)
    gemm_tile<<<dim3(256, 1, 8), 256>>>(node_state, INPD, 0,
                                        pe_w, 128, (long)INPD * UU,
                                        p_center, 128, 0,
                                        0, INPD, p_lists, p_cnt, nullptr, nullptr, 0, 1.f);

    // 6. qr = center @ Bk2   (N x 1024, K=128)
    gemm_tile<<<dim3(256, 8, 1), 256>>>(p_center, 128, 0, p_Bk2, 1024, 0,
                                        p_qr, 1024, 0,
                                        NN, 128, nullptr, nullptr, nullptr, nullptr, 0, 1.f);

    // 7. fused gather / scores / softmax / per-relation weighted sums
    edge_kernel<<<NN, 128>>>(adjacency, relation);

    // 8. out = center + relu(s @ Bv2 + fc_b)   (N x 128, K=1024)
    gemm_tile<<<dim3(256, 1, 1), 256>>>(p_s, 1024, 0, p_Bv2, 128, 0,
                                        out, 128, 0,
                                        NN, 1024, nullptr, nullptr, fc_b, p_center, 1, 1.f);
}

// round 7
// speedup vs baseline: 1.5276x; 1.5276x over previous
#include <cuda_runtime.h>
#include <cuda_bf16.h>
#include <cstdint>

#define NN  16384
#define DD  32
#define INPD 256
#define UU  128
#define RR  8
#define ENTT 8

// ---------------- scratch (device globals: no allocation allowed) ----------------
__device__ float g_center[NN * UU];            // (N, U)
__device__ float g_qr[NN * RR * UU];           // (N, R*U)  per-node per-relation query
__device__ float g_s[NN * RR * UU];            // (N, R*U)  attn-weighted neighbor sums
__device__ float g_kT[UU * UU];                // k_w^T
__device__ float g_relT[RR * UU * UU];         // rel_w[r]^T
__device__ float g_qk[UU * UU];                // q_w @ k_w^T
__device__ float g_vf[UU * UU];                // v_w @ fc_w
__device__ float g_Bk2[UU * RR * UU];          // (U, R*U): col r*128+a = (1/U) * qk @ rel_w[r]^T
__device__ float g_Bv2[RR * UU * UU];          // (R*U, U): rel_w[r] @ vf
__device__ int   g_cnt[ENTT];
__device__ int   g_lists[ENTT * NN];

// ======================= warp-level bf16 MMA (HMMA path, plain sm_103) =======================
__device__ __forceinline__ void mma_bf16(float* d,
                                         uint32_t a0, uint32_t a1, uint32_t a2, uint32_t a3,
                                         uint32_t b0, uint32_t b1)
{
    asm volatile(
        "mma.sync.aligned.m16n8k16.row.col.f32.bf16.bf16.f32 "
        "{%0,%1,%2,%3}, {%4,%5,%6,%7}, {%8,%9}, {%0,%1,%2,%3};"
        : "+f"(d[0]), "+f"(d[1]), "+f"(d[2]), "+f"(d[3])
        : "r"(a0), "r"(a1), "r"(a2), "r"(a3), "r"(b0), "r"(b1));
}

// C[128 tile] = A @ B with split-bf16 3-pass (full fp32-grade precision).
// A row-major [M,K] lda ; B row-major [K,N] ldb ; K % 32 == 0; M,N multiples of 128.
// Epilogue: +bias[col], relu, +addsrc[row*ldc+col] (each optional).
#define SROW 17   // b32 stride per 32-k row (16 data + 1 pad; odd -> conflict-free frags)

__global__ __launch_bounds__(256) void mma_gemm(
    const float* __restrict__ A, int lda,
    const float* __restrict__ B, int ldb,
    float* __restrict__ C, int ldc, int K,
    const float* __restrict__ bias, const float* __restrict__ addsrc, int do_relu)
{
    __shared__ uint32_t sA[2][128 * SROW];   // [hi/lo][row][k2]
    __shared__ uint32_t sB[2][128 * SROW];   // [hi/lo][n][k2]   (K-major == B col-major)

    const int tid  = threadIdx.x;
    const int lane = tid & 31;
    const int w    = tid >> 5;
    const int wm   = w >> 2;                 // 0..1 : 64 rows each
    const int wn   = w & 3;                  // 0..3 : 32 cols each
    const int m0   = blockIdx.x * 128;
    const int n0   = blockIdx.y * 128;

    float acc[4][4][4];
#pragma unroll
    for (int i = 0; i < 4; i++)
#pragma unroll
        for (int j = 0; j < 4; j++)
#pragma unroll
            for (int r = 0; r < 4; r++) acc[i][j][r] = 0.f;

    for (int kt = 0; kt < K; kt += 32) {
        // ---- A chunk: 128 rows x 32 k, fp32 -> bf16 hi/lo split ----
#pragma unroll
        for (int it = 0; it < 4; it++) {
            int lin = tid + it * 256;
            int row = lin >> 3;
            int f4  = lin & 7;
            float4 v = *reinterpret_cast<const float4*>(A + (long)(m0 + row) * lda + kt + f4 * 4);
            __nv_bfloat16 h0 = __float2bfloat16(v.x), h1 = __float2bfloat16(v.y);
            __nv_bfloat16 h2 = __float2bfloat16(v.z), h3 = __float2bfloat16(v.w);
            __nv_bfloat16 l0 = __float2bfloat16(v.x - __bfloat162float(h0));
            __nv_bfloat16 l1 = __float2bfloat16(v.y - __bfloat162float(h1));
            __nv_bfloat16 l2 = __float2bfloat16(v.z - __bfloat162float(h2));
            __nv_bfloat16 l3 = __float2bfloat16(v.w - __bfloat162float(h3));
            int idx = row * SROW + f4 * 2;
            sA[0][idx]     = ((uint32_t)__bfloat16_as_ushort(h1) << 16) | __bfloat16_as_ushort(h0);
            sA[0][idx + 1] = ((uint32_t)__bfloat16_as_ushort(h3) << 16) | __bfloat16_as_ushort(h2);
            sA[1][idx]     = ((uint32_t)__bfloat16_as_ushort(l1) << 16) | __bfloat16_as_ushort(l0);
            sA[1][idx + 1] = ((uint32_t)__bfloat16_as_ushort(l3) << 16) | __bfloat16_as_ushort(l2);
        }
        // ---- B chunk: 32 k x 128 n, transpose to [n][k] + split ----
#pragma unroll
        for (int it = 0; it < 4; it++) {
            int lin = tid + it * 256;
            int kk  = lin >> 5;
            int n4  = (lin & 31) * 4;
            float4 v = *reinterpret_cast<const float4*>(B + (long)(kt + kk) * ldb + n0 + n4);
            float vv[4] = {v.x, v.y, v.z, v.w};
            __nv_bfloat16* pH = reinterpret_cast<__nv_bfloat16*>(sB[0]);
            __nv_bfloat16* pL = reinterpret_cast<__nv_bfloat16*>(sB[1]);
#pragma unroll
            for (int j = 0; j < 4; j++) {
                __nv_bfloat16 h = __float2bfloat16(vv[j]);
                __nv_bfloat16 l = __float2bfloat16(vv[j] - __bfloat162float(h));
                int bidx = (n4 + j) * (2 * SROW) + kk;
                pH[bidx] = h;
                pL[bidx] = l;
            }
        }
        __syncthreads();

        // ---- MMA: 2 k16 steps x 3 passes (AhiBhi, AhiBlo, AloBhi) ----
#pragma unroll
        for (int st = 0; st < 2; st++) {
            int k2 = st * 8 + (lane & 3);
            uint32_t a[4][4];
#pragma unroll
            for (int p = 0; p < 3; p++) {
                const int hA = (p == 2) ? 1 : 0;
                const int hB = (p == 1) ? 1 : 0;
                if (p != 1) {                 // p==1 reuses p==0's A (hi) fragments
#pragma unroll
                    for (int i = 0; i < 4; i++) {
                        int r = wm * 64 + i * 16 + (lane >> 2);
                        a[i][0] = sA[hA][r * SROW + k2];
                        a[i][1] = sA[hA][(r + 8) * SROW + k2];
                        a[i][2] = sA[hA][r * SROW + k2 + 4];
                        a[i][3] = sA[hA][(r + 8) * SROW + k2 + 4];
                    }
                }
#pragma unroll
                for (int j = 0; j < 4; j++) {
                    int c = wn * 32 + j * 8 + (lane >> 2);
                    uint32_t b0 = sB[hB][c * SROW + k2];
                    uint32_t b1 = sB[hB][c * SROW + k2 + 4];
#pragma unroll
                    for (int i = 0; i < 4; i++)
                        mma_bf16(acc[i][j], a[i][0], a[i][1], a[i][2], a[i][3], b0, b1);
                }
            }
        }
        __syncthreads();
    }

    // ---- epilogue ----
#pragma unroll
    for (int i = 0; i < 4; i++) {
        int r0 = m0 + wm * 64 + i * 16 + (lane >> 2);
#pragma unroll
        for (int j = 0; j < 4; j++) {
            int cc = n0 + wn * 32 + j * 8 + (lane & 3) * 2;
            float bx = 0.f, by = 0.f;
            if (bias) { bx = bias[cc]; by = bias[cc + 1]; }
#pragma unroll
            for (int hrow = 0; hrow < 2; hrow++) {
                int rr = r0 + hrow * 8;
                float vx = acc[i][j][hrow * 2 + 0] + bx;
                float vy = acc[i][j][hrow * 2 + 1] + by;
                if (do_relu) { vx = fmaxf(vx, 0.f); vy = fmaxf(vy, 0.f); }
                if (addsrc) {
                    const float2 av = *reinterpret_cast<const float2*>(addsrc + (long)rr * ldc + cc);
                    vx += av.x; vy += av.y;
                }
                *reinterpret_cast<float2*>(C + (long)rr * ldc + cc) = make_float2(vx, vy);
            }
        }
    }
}

// ---------------- transpose k_w and rel_w[r] ----------------
__global__ void transpose_kernel(const float* __restrict__ k_w,
                                 const float* __restrict__ rel_w)
{
    int m = blockIdx.z;
    const float* src = (m == 0) ? k_w : (rel_w + (m - 1) * UU * UU);
    float* dst = (m == 0) ? g_kT : (g_relT + (m - 1) * UU * UU);
    __shared__ float t[32][33];
    int tx = threadIdx.x, ty = threadIdx.y;   // block (32, 8)
    int x = blockIdx.x * 32 + tx;
    int y0 = blockIdx.y * 32;
#pragma unroll
    for (int i = 0; i < 4; i++)
        t[ty + 8 * i][tx] = src[(y0 + ty + 8 * i) * UU + x];
    __syncthreads();
    int x2 = blockIdx.y * 32 + tx;
    int y2 = blockIdx.x * 32;
#pragma unroll
    for (int i = 0; i < 4; i++)
        dst[(y2 + ty + 8 * i) * UU + x2] = t[tx][ty + 8 * i];
}

// ---------------- entity partition ----------------
__global__ void zero_cnt_kernel() {
    if (threadIdx.x < ENTT) g_cnt[threadIdx.x] = 0;
}
__global__ void partition_kernel(const int* __restrict__ pe) {
    int n = blockIdx.x * blockDim.x + threadIdx.x;
    if (n < NN) {
        int e = pe[n];
        int pos = atomicAdd(&g_cnt[e], 1);
        g_lists[e * NN + pos] = n;
    }
}

// ---------------- generic 64x128x32 tiled fp32 GEMM (small/gathered cases) ----------------
__global__ __launch_bounds__(256) void gemm_tile(
    const float* __restrict__ A, int lda, long sAz,
    const float* __restrict__ B, int ldb, long sBz,
    float* __restrict__ C, int ldc, long sCz,
    int M, int K,
    const int* __restrict__ rowlists, const int* __restrict__ cnts,
    const float* __restrict__ bias, const float* __restrict__ addsrc,
    int do_relu, float alpha)
{
    __shared__ float As[64][33];
    __shared__ float Bs[32][128];
    __shared__ int rowidx[64];

    int z = blockIdx.z;
    A += z * sAz; B += z * sBz; C += z * sCz;
    int m0 = blockIdx.x * 64;
    int n0 = blockIdx.y * 128;
    int rows = rowlists ? cnts[z] : M;
    if (m0 >= rows) return;
    const int* rl = rowlists ? (rowlists + z * NN) : nullptr;

    int tid = threadIdx.x;
    if (tid < 64) {
        int g = m0 + tid;
        rowidx[tid] = (g < rows) ? (rl ? rl[g] : g) : -1;
    }
    __syncthreads();

    int tx = tid & 15, ty = tid >> 4;
    float acc[4][8];
#pragma unroll
    for (int i = 0; i < 4; i++)
#pragma unroll
        for (int j = 0; j < 8; j++) acc[i][j] = 0.f;

    for (int kt = 0; kt < K; kt += 32) {
#pragma unroll
        for (int j = 0; j < 8; j++) {          // A: 64x32
            int lin = tid + j * 256;
            int lr = lin >> 5, lc = lin & 31;
            int ar = rowidx[lr];
            As[lr][lc] = (ar >= 0) ? A[ar * lda + kt + lc] : 0.f;
        }
#pragma unroll
        for (int j = 0; j < 16; j++) {         // B: 32x128
            int lin = tid + j * 256;
            int br = lin >> 7, bc = lin & 127;
            Bs[br][bc] = B[(kt + br) * ldb + n0 + bc];
        }
        __syncthreads();
#pragma unroll
        for (int kk = 0; kk < 32; kk++) {
            float bv[8];
#pragma unroll
            for (int j = 0; j < 8; j++) bv[j] = Bs[kk][tx + 16 * j];
#pragma unroll
            for (int i = 0; i < 4; i++) {
                float av = As[ty * 4 + i][kk];
#pragma unroll
                for (int j = 0; j < 8; j++) acc[i][j] += av * bv[j];
            }
        }
        __syncthreads();
    }

#pragma unroll
    for (int i = 0; i < 4; i++) {
        int cr = rowidx[ty * 4 + i];
        if (cr < 0) continue;
#pragma unroll
        for (int j = 0; j < 8; j++) {
            int col = n0 + tx + 16 * j;
            float v = acc[i][j] * alpha;
            if (bias) v += bias[col];
            if (do_relu) v = fmaxf(v, 0.f);
            if (addsrc) v += addsrc[cr * ldc + col];
            C[cr * ldc + col] = v;
        }
    }
}

// ---------------- fused gather / score / softmax / weighted-scatter ----------------
__global__ __launch_bounds__(128) void edge_kernel(const int* __restrict__ adjacency,
                                                   const int* __restrict__ relation)
{
    __shared__ float xs[DD][UU];      // gathered neighbor embeddings
    __shared__ float aw[RR][DD];      // per-relation masked attention
    __shared__ float scores[DD];
    __shared__ int adjs[DD];
    __shared__ int rels[DD];

    int n = blockIdx.x;
    int tid = threadIdx.x, lane = tid & 31, w = tid >> 5;

    if (tid < DD) {
        adjs[tid] = adjacency[n * DD + tid];
        rels[tid] = relation[n * DD + tid];
    }
    __syncthreads();

    // gather x: warp w loads rows d = w*8 .. w*8+7 (float4, coalesced)
#pragma unroll
    for (int i = 0; i < 8; i++) {
        int d = w * 8 + i;
        int idx = adjs[d];
        float4 v = (idx > 0)
            ? reinterpret_cast<const float4*>(g_center + (idx - 1) * UU)[lane]
            : make_float4(0.f, 0.f, 0.f, 0.f);
        reinterpret_cast<float4*>(&xs[d][0])[lane] = v;
    }
    __syncwarp();

    // scores[d] = qr[n, rel[d]] . x[d]  (1/U already folded into g_Bk2)
    const float* qbase = g_qr + n * (RR * UU);
#pragma unroll
    for (int i = 0; i < 8; i++) {
        int d = w * 8 + i;
        int r = rels[d];
        const float* q = qbase + r * UU;
        float s = 0.f;
#pragma unroll
        for (int k2 = 0; k2 < 4; k2++) {
            int c = lane + 32 * k2;
            s += q[c] * xs[d][c];
        }
#pragma unroll
        for (int off = 16; off > 0; off >>= 1) s += __shfl_xor_sync(0xffffffffu, s, off);
        if (lane == 0) scores[d] = (r == 0) ? -1e9f : s;
    }
    __syncthreads();

    // softmax over D=32 (warp 0), then per-relation masked attention
    if (w == 0) {
        float v = scores[lane];
        float m = v;
#pragma unroll
        for (int off = 16; off > 0; off >>= 1) m = fmaxf(m, __shfl_xor_sync(0xffffffffu, m, off));
        float e = __expf(v - m);
        float sum = e;
#pragma unroll
        for (int off = 16; off > 0; off >>= 1) sum += __shfl_xor_sync(0xffffffffu, sum, off);
        float a = e / sum;
        int r = rels[lane];
#pragma unroll
        for (int rr = 0; rr < RR; rr++) aw[rr][lane] = (r == rr) ? a : 0.f;
    }
    __syncthreads();

    // s[n, r, :] = sum_d aw[r][d] * x[d, :]
    float acc[RR];
#pragma unroll
    for (int r = 0; r < RR; r++) acc[r] = 0.f;
#pragma unroll
    for (int d = 0; d < DD; d++) {
        float x = xs[d][tid];
#pragma unroll
        for (int r = 0; r < RR; r++) acc[r] += aw[r][d] * x;
    }
    float* sp = g_s + n * (RR * UU) + tid;
#pragma unroll
    for (int r = 0; r < RR; r++) sp[r * UU] = acc[r];
}

// ---------------- launch ----------------
extern "C" void kernel_launch(void* const* d_in, const int* in_sizes, int n_in,
                              void* d_out, int out_size)
{
    const float* node_state = (const float*)d_in[0];
    const int*   adjacency  = (const int*)d_in[1];
    const int*   point_enc  = (const int*)d_in[2];
    const int*   relation   = (const int*)d_in[3];
    const float* pe_w       = (const float*)d_in[4];
    const float* rel_w      = (const float*)d_in[5];
    const float* q_w        = (const float*)d_in[6];
    const float* k_w        = (const float*)d_in[7];
    const float* v_w        = (const float*)d_in[8];
    const float* fc_w       = (const float*)d_in[9];
    const float* fc_b       = (const float*)d_in[10];
    float* out = (float*)d_out;

    float *p_center, *p_qr, *p_s, *p_kT, *p_relT, *p_qk, *p_vf, *p_Bk2, *p_Bv2;
    int *p_cnt, *p_lists;
    cudaGetSymbolAddress((void**)&p_center, g_center);
    cudaGetSymbolAddress((void**)&p_qr,     g_qr);
    cudaGetSymbolAddress((void**)&p_s,      g_s);
    cudaGetSymbolAddress((void**)&p_kT,     g_kT);
    cudaGetSymbolAddress((void**)&p_relT,   g_relT);
    cudaGetSymbolAddress((void**)&p_qk,     g_qk);
    cudaGetSymbolAddress((void**)&p_vf,     g_vf);
    cudaGetSymbolAddress((void**)&p_Bk2,    g_Bk2);
    cudaGetSymbolAddress((void**)&p_Bv2,    g_Bv2);
    cudaGetSymbolAddress((void**)&p_cnt,    g_cnt);
    cudaGetSymbolAddress((void**)&p_lists,  g_lists);

    // 1. transposes of k_w and rel_w[r]
    transpose_kernel<<<dim3(4, 4, 9), dim3(32, 8)>>>(k_w, rel_w);

    // 2. qk = q_w @ k_w^T ; vf = v_w @ fc_w
    gemm_tile<<<dim3(2, 1, 1), 256>>>(q_w, 128, 0, p_kT, 128, 0, p_qk, 128, 0,
                                      128, 128, nullptr, nullptr, nullptr, nullptr, 0, 1.f);
    gemm_tile<<<dim3(2, 1, 1), 256>>>(v_w, 128, 0, fc_w, 128, 0, p_vf, 128, 0,
                                      128, 128, nullptr, nullptr, nullptr, nullptr, 0, 1.f);

    // 3. Bk2[:, r*128+a] = (1/U) * qk @ rel_w[r]^T ; Bv2[r*128+a, :] = rel_w[r] @ vf
    gemm_tile<<<dim3(2, 1, 8), 256>>>(p_qk, 128, 0, p_relT, 128, (long)UU * UU,
                                      p_Bk2, 1024, 128,
                                      128, 128, nullptr, nullptr, nullptr, nullptr, 0, 1.f / 128.f);
    gemm_tile<<<dim3(2, 1, 8), 256>>>(rel_w, 128, (long)UU * UU, p_vf, 128, 0,
                                      p_Bv2, 128, (long)UU * UU,
                                      128, 128, nullptr, nullptr, nullptr, nullptr, 0, 1.f);

    // 4. entity partition
    zero_cnt_kernel<<<1, 32>>>();
    partition_kernel<<<NN / 256, 256>>>(point_enc);

    // 5. center[n] = node_state[n] @ point_enc_w[point_enc[n]]   (gathered GEMM per entity)
    gemm_tile<<<dim3(256, 1, 8), 256>>>(node_state, INPD, 0,
                                        pe_w, 128, (long)INPD * UU,
                                        p_center, 128, 0,
                                        0, INPD, p_lists, p_cnt, nullptr, nullptr, 0, 1.f);

    // 6. qr = center @ Bk2   (N x 1024, K=128)  — warp-MMA split-bf16
    mma_gemm<<<dim3(128, 8), 256>>>(p_center, 128, p_Bk2, 1024,
                                    p_qr, 1024, 128,
                                    nullptr, nullptr, 0);

    // 7. fused gather / scores / softmax / per-relation weighted sums
    edge_kernel<<<NN, 128>>>(adjacency, relation);

    // 8. out = center + relu(s @ Bv2 + fc_b)   (N x 128, K=1024)  — warp-MMA split-bf16
    mma_gemm<<<dim3(128, 1), 256>>>(p_s, 1024, p_Bv2, 128,
                                    out, 128, 1024,
                                    fc_b, p_center, 1);
}

// round 9
// speedup vs baseline: 1.6524x; 1.0817x over previous
#include <cuda_runtime.h>
#include <cuda_bf16.h>
#include <cstdint>

#define NN  16384
#define DD  32
#define INPD 256
#define UU  128
#define RR  8
#define ENTT 8

// ---------------- scratch (device globals: no allocation allowed) ----------------
__device__ float g_center[NN * UU];            // (N, U)
__device__ float g_qr[NN * RR * UU];           // (N, R*U)  per-node per-relation query
__device__ float g_s[NN * RR * UU];            // (N, R*U)  attn-weighted neighbor sums
__device__ float g_T[RR * UU * UU];            // T[r] = rel[r] @ k_w
__device__ float g_S[RR * UU * UU];            // S[r] = rel[r] @ v_w
__device__ float g_Bk2[UU * RR * UU];          // (U, R*U)
__device__ float g_Bv2[RR * UU * UU];          // (R*U, U)
__device__ int   g_cnt[ENTT];
__device__ int   g_lists[ENTT * NN];

// ======================= warp-level bf16 MMA (HMMA path, plain sm_103) =======================
__device__ __forceinline__ void mma_bf16(float* d,
                                         uint32_t a0, uint32_t a1, uint32_t a2, uint32_t a3,
                                         uint32_t b0, uint32_t b1)
{
    asm volatile(
        "mma.sync.aligned.m16n8k16.row.col.f32.bf16.bf16.f32 "
        "{%0,%1,%2,%3}, {%4,%5,%6,%7}, {%8,%9}, {%0,%1,%2,%3};"
        : "+f"(d[0]), "+f"(d[1]), "+f"(d[2]), "+f"(d[3])
        : "r"(a0), "r"(a1), "r"(a2), "r"(a3), "r"(b0), "r"(b1));
}

// C[128 tile] = A @ B with split-bf16 3-pass (fp32-grade precision).
// A row-major [M,K] lda ; B row-major [K,N] ldb (+ z*sBz) ; K % 32 == 0.
// Optional row gather: rowlists/cnts per blockIdx.z (rows are GLOBAL indices; scatter on store).
// Epilogue: +bias[col], relu, +addsrc[row*ldc+col] (each optional).
#define SROW 17   // b32 stride per 32-k row (16 data + 1 pad; odd -> conflict-free frags)

__global__ __launch_bounds__(256) void mma_gemm(
    const float* __restrict__ A, int lda,
    const float* __restrict__ B, int ldb, long sBz,
    float* __restrict__ C, int ldc, int K,
    const int* __restrict__ rowlists, const int* __restrict__ cnts,
    const float* __restrict__ bias, const float* __restrict__ addsrc, int do_relu)
{
    __shared__ uint32_t sA[2][128 * SROW];   // [hi/lo][row][k2]
    __shared__ uint32_t sB[2][128 * SROW];   // [hi/lo][n][k2]   (K-major == B col-major)
    __shared__ int rowidx[128];

    const int tid  = threadIdx.x;
    const int lane = tid & 31;
    const int w    = tid >> 5;
    const int wm   = w >> 2;                 // 0..1 : 64 rows each
    const int wn   = w & 3;                  // 0..3 : 32 cols each
    const int m0   = blockIdx.x * 128;
    const int n0   = blockIdx.y * 128;
    const int z    = blockIdx.z;

    int rows = 0x40000000;
    const int* rl = nullptr;
    if (rowlists) {
        rows = cnts[z];
        if (m0 >= rows) return;
        rl = rowlists + z * NN;
    }
    B += z * sBz;

    if (tid < 128) {
        int g = m0 + tid;
        rowidx[tid] = rl ? ((g < rows) ? rl[g] : -1) : g;
    }
    __syncthreads();

    float acc[4][4][4];
#pragma unroll
    for (int i = 0; i < 4; i++)
#pragma unroll
        for (int j = 0; j < 4; j++)
#pragma unroll
            for (int r = 0; r < 4; r++) acc[i][j][r] = 0.f;

    for (int kt = 0; kt < K; kt += 32) {
        // ---- A chunk: 128 rows x 32 k, fp32 -> bf16 hi/lo split ----
#pragma unroll
        for (int it = 0; it < 4; it++) {
            int lin = tid + it * 256;
            int row = lin >> 3;
            int f4  = lin & 7;
            int ar  = rowidx[row];
            float4 v = (ar >= 0)
                ? *reinterpret_cast<const float4*>(A + (long)ar * lda + kt + f4 * 4)
                : make_float4(0.f, 0.f, 0.f, 0.f);
            __nv_bfloat16 h0 = __float2bfloat16(v.x), h1 = __float2bfloat16(v.y);
            __nv_bfloat16 h2 = __float2bfloat16(v.z), h3 = __float2bfloat16(v.w);
            __nv_bfloat16 l0 = __float2bfloat16(v.x - __bfloat162float(h0));
            __nv_bfloat16 l1 = __float2bfloat16(v.y - __bfloat162float(h1));
            __nv_bfloat16 l2 = __float2bfloat16(v.z - __bfloat162float(h2));
            __nv_bfloat16 l3 = __float2bfloat16(v.w - __bfloat162float(h3));
            int idx = row * SROW + f4 * 2;
            sA[0][idx]     = ((uint32_t)__bfloat16_as_ushort(h1) << 16) | __bfloat16_as_ushort(h0);
            sA[0][idx + 1] = ((uint32_t)__bfloat16_as_ushort(h3) << 16) | __bfloat16_as_ushort(h2);
            sA[1][idx]     = ((uint32_t)__bfloat16_as_ushort(l1) << 16) | __bfloat16_as_ushort(l0);
            sA[1][idx + 1] = ((uint32_t)__bfloat16_as_ushort(l3) << 16) | __bfloat16_as_ushort(l2);
        }
        // ---- B chunk: 32 k x 128 n, transpose to [n][k] + split ----
#pragma unroll
        for (int it = 0; it < 4; it++) {
            int lin = tid + it * 256;
            int kk  = lin >> 5;
            int n4  = (lin & 31) * 4;
            float4 v = *reinterpret_cast<const float4*>(B + (long)(kt + kk) * ldb + n0 + n4);
            float vv[4] = {v.x, v.y, v.z, v.w};
            __nv_bfloat16* pH = reinterpret_cast<__nv_bfloat16*>(sB[0]);
            __nv_bfloat16* pL = reinterpret_cast<__nv_bfloat16*>(sB[1]);
#pragma unroll
            for (int j = 0; j < 4; j++) {
                __nv_bfloat16 h = __float2bfloat16(vv[j]);
                __nv_bfloat16 l = __float2bfloat16(vv[j] - __bfloat162float(h));
                int bidx = (n4 + j) * (2 * SROW) + kk;
                pH[bidx] = h;
                pL[bidx] = l;
            }
        }
        __syncthreads();

        // ---- MMA: 2 k16 steps x 3 passes (AhiBhi, AhiBlo, AloBhi) ----
#pragma unroll
        for (int st = 0; st < 2; st++) {
            int k2 = st * 8 + (lane & 3);
            uint32_t a[4][4];
#pragma unroll
            for (int p = 0; p < 3; p++) {
                const int hA = (p == 2) ? 1 : 0;
                const int hB = (p == 1) ? 1 : 0;
                if (p != 1) {                 // p==1 reuses p==0's A (hi) fragments
#pragma unroll
                    for (int i = 0; i < 4; i++) {
                        int r = wm * 64 + i * 16 + (lane >> 2);
                        a[i][0] = sA[hA][r * SROW + k2];
                        a[i][1] = sA[hA][(r + 8) * SROW + k2];
                        a[i][2] = sA[hA][r * SROW + k2 + 4];
                        a[i][3] = sA[hA][(r + 8) * SROW + k2 + 4];
                    }
                }
#pragma unroll
                for (int j = 0; j < 4; j++) {
                    int c = wn * 32 + j * 8 + (lane >> 2);
                    uint32_t b0 = sB[hB][c * SROW + k2];
                    uint32_t b1 = sB[hB][c * SROW + k2 + 4];
#pragma unroll
                    for (int i = 0; i < 4; i++)
                        mma_bf16(acc[i][j], a[i][0], a[i][1], a[i][2], a[i][3], b0, b1);
                }
            }
        }
        __syncthreads();
    }

    // ---- epilogue (scatter rows via rowidx) ----
#pragma unroll
    for (int i = 0; i < 4; i++) {
        int lr0 = wm * 64 + i * 16 + (lane >> 2);
#pragma unroll
        for (int j = 0; j < 4; j++) {
            int cc = n0 + wn * 32 + j * 8 + (lane & 3) * 2;
            float bx = 0.f, by = 0.f;
            if (bias) { bx = bias[cc]; by = bias[cc + 1]; }
#pragma unroll
            for (int hrow = 0; hrow < 2; hrow++) {
                int rr = rowidx[lr0 + hrow * 8];
                if (rr < 0) continue;
                float vx = acc[i][j][hrow * 2 + 0] + bx;
                float vy = acc[i][j][hrow * 2 + 1] + by;
                if (do_relu) { vx = fmaxf(vx, 0.f); vy = fmaxf(vy, 0.f); }
                if (addsrc) {
                    const float2 av = *reinterpret_cast<const float2*>(addsrc + (long)rr * ldc + cc);
                    vx += av.x; vy += av.y;
                }
                *reinterpret_cast<float2*>(C + (long)rr * ldc + cc) = make_float2(vx, vy);
            }
        }
    }
}

// ---------------- 64x128x128 SIMT tile for the tiny prep GEMMs ----------------
// C[64,128] = alpha * A[64,128] @ op(B);  transB: contract over B's 2nd index (B is [n][k]).
__device__ __forceinline__ void gemm64(const float* __restrict__ A,
                                       const float* __restrict__ B,
                                       float* __restrict__ C,
                                       int ldc, float alpha, int transB)
{
    __shared__ float As[64][33];
    __shared__ float Bs[32][128];
    int tid = threadIdx.x, tx = tid & 15, ty = tid >> 4;
    float acc[4][8];
#pragma unroll
    for (int i = 0; i < 4; i++)
#pragma unroll
        for (int j = 0; j < 8; j++) acc[i][j] = 0.f;

    for (int kt = 0; kt < 128; kt += 32) {
#pragma unroll
        for (int j = 0; j < 8; j++) {
            int lin = tid + j * 256;
            int lr = lin >> 5, lc = lin & 31;
            As[lr][lc] = A[lr * 128 + kt + lc];
        }
#pragma unroll
        for (int j = 0; j < 16; j++) {
            int lin = tid + j * 256;
            int br = lin >> 7, bc = lin & 127;
            Bs[br][bc] = transB ? B[bc * 128 + kt + br] : B[(kt + br) * 128 + bc];
        }
        __syncthreads();
#pragma unroll
        for (int kk = 0; kk < 32; kk++) {
            float bv[8];
#pragma unroll
            for (int j = 0; j < 8; j++) bv[j] = Bs[kk][tx + 16 * j];
#pragma unroll
            for (int i = 0; i < 4; i++) {
                float av = As[ty * 4 + i][kk];
#pragma unroll
                for (int j = 0; j < 8; j++) acc[i][j] += av * bv[j];
            }
        }
        __syncthreads();
    }
#pragma unroll
    for (int i = 0; i < 4; i++)
#pragma unroll
        for (int j = 0; j < 8; j++)
            C[(ty * 4 + i) * ldc + tx + 16 * j] = acc[i][j] * alpha;
}

// P1: T[r] = rel[r] @ k_w ; S[r] = rel[r] @ v_w   (grid (2,1,16)); also zeroes g_cnt.
__global__ __launch_bounds__(256) void prep1_kernel(const float* __restrict__ rel_w,
                                                    const float* __restrict__ k_w,
                                                    const float* __restrict__ v_w)
{
    if (blockIdx.x == 0 && blockIdx.z == 0 && threadIdx.x < ENTT) g_cnt[threadIdx.x] = 0;
    int z = blockIdx.z, r = z & 7, ph = z >> 3;
    const float* A = rel_w + r * (UU * UU) + blockIdx.x * 64 * UU;
    const float* B = ph ? v_w : k_w;
    float* C = (ph ? g_S : g_T) + r * (UU * UU) + blockIdx.x * 64 * UU;
    gemm64(A, B, C, UU, 1.f, 0);
}

// P2: Bk2[a, r*128+b] = (1/U) sum_e q_w[a,e] T[r][b,e]  (NT) ;  Bv2[r] = S[r] @ fc_w  (NN).
__global__ __launch_bounds__(256) void prep2_kernel(const float* __restrict__ q_w,
                                                    const float* __restrict__ fc_w)
{
    int z = blockIdx.z, r = z & 7, ph = z >> 3;
    if (!ph) {
        const float* A = q_w + blockIdx.x * 64 * UU;
        const float* B = g_T + r * (UU * UU);
        float* C = g_Bk2 + blockIdx.x * 64 * (RR * UU) + r * UU;
        gemm64(A, B, C, RR * UU, 1.f / 128.f, 1);
    } else {
        const float* A = g_S + r * (UU * UU) + blockIdx.x * 64 * UU;
        float* C = g_Bv2 + r * (UU * UU) + blockIdx.x * 64 * UU;
        gemm64(A, fc_w, C, UU, 1.f, 0);
    }
}

// ---------------- entity partition ----------------
__global__ void partition_kernel(const int* __restrict__ pe) {
    int n = blockIdx.x * blockDim.x + threadIdx.x;
    if (n < NN) {
        int e = pe[n];
        int pos = atomicAdd(&g_cnt[e], 1);
        g_lists[e * NN + pos] = n;
    }
}

// ---------------- fused gather / score / softmax / weighted-scatter ----------------
__global__ __launch_bounds__(128) void edge_kernel(const int* __restrict__ adjacency,
                                                   const int* __restrict__ relation)
{
    __shared__ float xs[DD][UU];      // gathered neighbor embeddings
    __shared__ float aw[RR][DD];      // per-relation masked attention
    __shared__ float scores[DD];
    __shared__ int adjs[DD];
    __shared__ int rels[DD];

    int n = blockIdx.x;
    int tid = threadIdx.x, lane = tid & 31, w = tid >> 5;

    if (tid < DD) {
        adjs[tid] = adjacency[n * DD + tid];
        rels[tid] = relation[n * DD + tid];
    }
    __syncthreads();

    // gather x: warp w loads rows d = w*8 .. w*8+7 (float4, coalesced)
#pragma unroll
    for (int i = 0; i < 8; i++) {
        int d = w * 8 + i;
        int idx = adjs[d];
        float4 v = (idx > 0)
            ? reinterpret_cast<const float4*>(g_center + (idx - 1) * UU)[lane]
            : make_float4(0.f, 0.f, 0.f, 0.f);
        reinterpret_cast<float4*>(&xs[d][0])[lane] = v;
    }
    __syncwarp();

    // scores[d] = qr[n, rel[d]] . x[d]  (1/U already folded into g_Bk2)
    const float* qbase = g_qr + n * (RR * UU);
#pragma unroll
    for (int i = 0; i < 8; i++) {
        int d = w * 8 + i;
        int r = rels[d];
        const float* q = qbase + r * UU;
        float s = 0.f;
#pragma unroll
        for (int k2 = 0; k2 < 4; k2++) {
            int c = lane + 32 * k2;
            s += q[c] * xs[d][c];
        }
#pragma unroll
        for (int off = 16; off > 0; off >>= 1) s += __shfl_xor_sync(0xffffffffu, s, off);
        if (lane == 0) scores[d] = (r == 0) ? -1e9f : s;
    }
    __syncthreads();

    // softmax over D=32 (warp 0), then per-relation masked attention
    if (w == 0) {
        float v = scores[lane];
        float m = v;
#pragma unroll
        for (int off = 16; off > 0; off >>= 1) m = fmaxf(m, __shfl_xor_sync(0xffffffffu, m, off));
        float e = __expf(v - m);
        float sum = e;
#pragma unroll
        for (int off = 16; off > 0; off >>= 1) sum += __shfl_xor_sync(0xffffffffu, sum, off);
        float a = e / sum;
        int r = rels[lane];
#pragma unroll
        for (int rr = 0; rr < RR; rr++) aw[rr][lane] = (r == rr) ? a : 0.f;
    }
    __syncthreads();

    // s[n, r, :] = sum_d aw[r][d] * x[d, :]
    float acc[RR];
#pragma unroll
    for (int r = 0; r < RR; r++) acc[r] = 0.f;
#pragma unroll
    for (int d = 0; d < DD; d++) {
        float x = xs[d][tid];
#pragma unroll
        for (int r = 0; r < RR; r++) acc[r] += aw[r][d] * x;
    }
    float* sp = g_s + n * (RR * UU) + tid;
#pragma unroll
    for (int r = 0; r < RR; r++) sp[r * UU] = acc[r];
}

// ---------------- launch ----------------
extern "C" void kernel_launch(void* const* d_in, const int* in_sizes, int n_in,
                              void* d_out, int out_size)
{
    const float* node_state = (const float*)d_in[0];
    const int*   adjacency  = (const int*)d_in[1];
    const int*   point_enc  = (const int*)d_in[2];
    const int*   relation   = (const int*)d_in[3];
    const float* pe_w       = (const float*)d_in[4];
    const float* rel_w      = (const float*)d_in[5];
    const float* q_w        = (const float*)d_in[6];
    const float* k_w        = (const float*)d_in[7];
    const float* v_w        = (const float*)d_in[8];
    const float* fc_w       = (const float*)d_in[9];
    const float* fc_b       = (const float*)d_in[10];
    float* out = (float*)d_out;

    float *p_center, *p_qr, *p_s, *p_Bk2, *p_Bv2;
    int *p_cnt, *p_lists;
    cudaGetSymbolAddress((void**)&p_center, g_center);
    cudaGetSymbolAddress((void**)&p_qr,     g_qr);
    cudaGetSymbolAddress((void**)&p_s,      g_s);
    cudaGetSymbolAddress((void**)&p_Bk2,    g_Bk2);
    cudaGetSymbolAddress((void**)&p_Bv2,    g_Bv2);
    cudaGetSymbolAddress((void**)&p_cnt,    g_cnt);
    cudaGetSymbolAddress((void**)&p_lists,  g_lists);

    // 1. prep chain (depth 2): T/S then Bk2/Bv2 ; P1 also zeroes g_cnt
    prep1_kernel<<<dim3(2, 1, 16), 256>>>(rel_w, k_w, v_w);
    // 2. entity partition (needs g_cnt zeroed by P1)
    partition_kernel<<<NN / 256, 256>>>(point_enc);
    // 3. prep stage 2
    prep2_kernel<<<dim3(2, 1, 16), 256>>>(q_w, fc_w);

    // 4. center[n] = node_state[n] @ point_enc_w[point_enc[n]]  — gathered warp-MMA
    mma_gemm<<<dim3(32, 1, 8), 256>>>(node_state, INPD, pe_w, 128, (long)INPD * UU,
                                      p_center, 128, INPD,
                                      p_lists, p_cnt, nullptr, nullptr, 0);

    // 5. qr = center @ Bk2   (N x 1024, K=128)  — warp-MMA split-bf16
    mma_gemm<<<dim3(128, 8, 1), 256>>>(p_center, 128, p_Bk2, 1024, 0L,
                                       p_qr, 1024, 128,
                                       nullptr, nullptr, nullptr, nullptr, 0);

    // 6. fused gather / scores / softmax / per-relation weighted sums
    edge_kernel<<<NN, 128>>>(adjacency, relation);

    // 7. out = center + relu(s @ Bv2 + fc_b)   (N x 128, K=1024)  — warp-MMA split-bf16
    mma_gemm<<<dim3(128, 1, 1), 256>>>(p_s, 1024, p_Bv2, 128, 0L,
                                       out, 128, 1024,
                                       nullptr, nullptr, fc_b, p_center, 1);
}

// round 10
// speedup vs baseline: 1.8492x; 1.1191x over previous
#include <cuda_runtime.h>
#include <cuda_bf16.h>
#include <cstdint>

#define NN  16384
#define DD  32
#define INPD 256
#define UU  128
#define RR  8
#define ENTT 8

// ---------------- scratch (device globals: no allocation allowed) ----------------
__device__ float g_center[NN * UU];            // (N, U)
__device__ float g_qr[NN * RR * UU];           // (N, R*U)
__device__ float g_s[NN * RR * UU];            // (N, R*U)
__device__ float g_T[RR * UU * UU];            // T[r] = rel[r] @ k_w
__device__ float g_S[RR * UU * UU];            // S[r] = rel[r] @ v_w
__device__ float g_Bk2[UU * RR * UU];          // (U, R*U)
__device__ float g_Bv2[RR * UU * UU];          // (R*U, U)
__device__ int   g_cnt[ENTT];
__device__ int   g_lists[ENTT * NN];

// ======================= warp-level bf16 MMA (HMMA path, plain sm_103) =======================
__device__ __forceinline__ void mma_bf16(float* d,
                                         uint32_t a0, uint32_t a1, uint32_t a2, uint32_t a3,
                                         uint32_t b0, uint32_t b1)
{
    asm volatile(
        "mma.sync.aligned.m16n8k16.row.col.f32.bf16.bf16.f32 "
        "{%0,%1,%2,%3}, {%4,%5,%6,%7}, {%8,%9}, {%0,%1,%2,%3};"
        : "+f"(d[0]), "+f"(d[1]), "+f"(d[2]), "+f"(d[3])
        : "r"(a0), "r"(a1), "r"(a2), "r"(a3), "r"(b0), "r"(b1));
}

__device__ __forceinline__ void cp16(uint32_t dst, const void* src, int sz) {
    asm volatile("cp.async.ca.shared.global [%0], [%1], 16, %2;"
                 :: "r"(dst), "l"(src), "r"(sz) : "memory");
}
#define CP_COMMIT() asm volatile("cp.async.commit_group;" ::: "memory")
#define CP_WAIT1()  asm volatile("cp.async.wait_group 1;" ::: "memory")
#define CP_WAIT0()  asm volatile("cp.async.wait_group 0;" ::: "memory")

#define SROW 17   // b32 stride per 32-k row (16 data + 1 pad; odd -> conflict-free frags)

// Dynamic smem layout (bytes):
//   [0,512)                      rowidx (MT ints)
//   [512, 512+MT*256)            rawA double buffer (2 x MT x 32 fp32)
//   [+, +32768)                  rawB double buffer (2 x 32 x 128 fp32)
//   [+, +2*MT*SROW*4)            sA hi|lo (bf16x2 packed, [row][k2])
//   [+, +2*128*SROW*4)           sB hi|lo ([n][k2])
#define SMEM_MMA(MT) (512 + (MT)*256 + 32768 + 2*(MT)*SROW*4 + 2*128*SROW*4)

// C tile (MT x 128) = A @ B, split-bf16 3-pass, cp.async 2-stage pipelined.
// A row-major [M,K] lda ; B row-major [K,N] ldb (+ z*sBz) ; K % 32 == 0.
// Optional row gather (rowlists/cnts per blockIdx.z); epilogue: +bias, relu, +addsrc.
template<int MT>
__global__ __launch_bounds__(256) void mma_gemm(
    const float* __restrict__ A, int lda,
    const float* __restrict__ B, int ldb, long sBz,
    float* __restrict__ C, int ldc, int K,
    const int* __restrict__ rowlists, const int* __restrict__ cnts,
    const float* __restrict__ bias, const float* __restrict__ addsrc, int do_relu)
{
    constexpr int NI = MT / 32;          // per-warp row blocks (16 rows each) & A-iter count
    extern __shared__ char smem[];
    int*      rowidx = (int*)smem;
    float*    rawA   = (float*)(smem + 512);
    float*    rawB   = (float*)(smem + 512 + MT * 256);
    uint32_t* sAb    = (uint32_t*)(smem + 512 + MT * 256 + 32768);  // hi at 0, lo at +MT*SROW
    uint32_t* sBb    = sAb + 2 * MT * SROW;                          // hi at 0, lo at +128*SROW

    const int tid  = threadIdx.x;
    const int lane = tid & 31;
    const int w    = tid >> 5;
    const int wm   = w >> 2;
    const int wn   = w & 3;
    const int m0   = blockIdx.x * MT;
    const int n0   = blockIdx.y * 128;
    const int z    = blockIdx.z;

    int rows = 0x40000000;
    const int* rl = nullptr;
    if (rowlists) {
        rows = cnts[z];
        if (m0 >= rows) return;
        rl = rowlists + z * NN;
    }
    B += z * sBz;

    if (tid < MT) {
        int g = m0 + tid;
        rowidx[tid] = rl ? ((g < rows) ? rl[g] : -1) : g;
    }
    __syncthreads();

    float acc[NI][4][4];
#pragma unroll
    for (int i = 0; i < NI; i++)
#pragma unroll
        for (int j = 0; j < 4; j++)
#pragma unroll
            for (int r = 0; r < 4; r++) acc[i][j][r] = 0.f;

    const int nk = K / 32;

    // ---- prologue: issue chunk 0 ----
    {
#pragma unroll
        for (int it = 0; it < NI; it++) {
            int lin = tid + it * 256;
            int row = lin >> 3, f4 = lin & 7;
            int ar = rowidx[row];
            const float* src = (ar >= 0) ? (A + (long)ar * lda + f4 * 4) : A;
            cp16((uint32_t)__cvta_generic_to_shared(rawA + row * 32 + f4 * 4), src,
                 (ar >= 0) ? 16 : 0);
        }
#pragma unroll
        for (int it = 0; it < 4; it++) {
            int lin = tid + it * 256;
            int kk = lin >> 5, n4 = (lin & 31) * 4;
            cp16((uint32_t)__cvta_generic_to_shared(rawB + kk * 128 + n4),
                 B + (long)kk * ldb + n0 + n4, 16);
        }
        CP_COMMIT();
    }

    for (int kt = 0; kt < nk; kt++) {
        const int cur = kt & 1;
        if (kt + 1 < nk) {
            const int nxt = cur ^ 1;
            const int k0 = (kt + 1) * 32;
#pragma unroll
            for (int it = 0; it < NI; it++) {
                int lin = tid + it * 256;
                int row = lin >> 3, f4 = lin & 7;
                int ar = rowidx[row];
                const float* src = (ar >= 0) ? (A + (long)ar * lda + k0 + f4 * 4) : A;
                cp16((uint32_t)__cvta_generic_to_shared(rawA + nxt * MT * 32 + row * 32 + f4 * 4),
                     src, (ar >= 0) ? 16 : 0);
            }
#pragma unroll
            for (int it = 0; it < 4; it++) {
                int lin = tid + it * 256;
                int kk = lin >> 5, n4 = (lin & 31) * 4;
                cp16((uint32_t)__cvta_generic_to_shared(rawB + nxt * 4096 + kk * 128 + n4),
                     B + (long)(k0 + kk) * ldb + n0 + n4, 16);
            }
            CP_COMMIT();
            CP_WAIT1();
        } else {
            CP_WAIT0();
        }
        __syncthreads();   // chunk kt staged; previous MMA done reading sA/sB

        // ---- convert A: raw fp32 -> bf16 hi/lo packed ----
        const float* rA = rawA + cur * MT * 32;
#pragma unroll
        for (int it = 0; it < NI; it++) {
            int lin = tid + it * 256;
            int row = lin >> 3, f4 = lin & 7;
            float4 v = *reinterpret_cast<const float4*>(rA + row * 32 + f4 * 4);
            __nv_bfloat16 h0 = __float2bfloat16(v.x), h1 = __float2bfloat16(v.y);
            __nv_bfloat16 h2 = __float2bfloat16(v.z), h3 = __float2bfloat16(v.w);
            __nv_bfloat16 l0 = __float2bfloat16(v.x - __bfloat162float(h0));
            __nv_bfloat16 l1 = __float2bfloat16(v.y - __bfloat162float(h1));
            __nv_bfloat16 l2 = __float2bfloat16(v.z - __bfloat162float(h2));
            __nv_bfloat16 l3 = __float2bfloat16(v.w - __bfloat162float(h3));
            int idx = row * SROW + f4 * 2;
            sAb[idx]                 = ((uint32_t)__bfloat16_as_ushort(h1) << 16) | __bfloat16_as_ushort(h0);
            sAb[idx + 1]             = ((uint32_t)__bfloat16_as_ushort(h3) << 16) | __bfloat16_as_ushort(h2);
            sAb[MT * SROW + idx]     = ((uint32_t)__bfloat16_as_ushort(l1) << 16) | __bfloat16_as_ushort(l0);
            sAb[MT * SROW + idx + 1] = ((uint32_t)__bfloat16_as_ushort(l3) << 16) | __bfloat16_as_ushort(l2);
        }
        // ---- convert B: transpose to [n][k] + split ----
        const float* rB = rawB + cur * 4096;
#pragma unroll
        for (int it = 0; it < 4; it++) {
            int lin = tid + it * 256;
            int kk = lin >> 5, n4 = (lin & 31) * 4;
            float4 v = *reinterpret_cast<const float4*>(rB + kk * 128 + n4);
            float vv[4] = {v.x, v.y, v.z, v.w};
            __nv_bfloat16* pH = reinterpret_cast<__nv_bfloat16*>(sBb);
            __nv_bfloat16* pL = reinterpret_cast<__nv_bfloat16*>(sBb + 128 * SROW);
#pragma unroll
            for (int j = 0; j < 4; j++) {
                __nv_bfloat16 h = __float2bfloat16(vv[j]);
                __nv_bfloat16 l = __float2bfloat16(vv[j] - __bfloat162float(h));
                int bidx = (n4 + j) * (2 * SROW) + kk;
                pH[bidx] = h;
                pL[bidx] = l;
            }
        }
        __syncthreads();   // sA/sB ready

        // ---- MMA: 2 k16 steps x 3 passes (AhiBhi, AhiBlo, AloBhi) ----
#pragma unroll
        for (int st = 0; st < 2; st++) {
            int k2 = st * 8 + (lane & 3);
            uint32_t a[NI][4];
#pragma unroll
            for (int p = 0; p < 3; p++) {
                const uint32_t* pA = sAb + ((p == 2) ? MT * SROW : 0);
                const uint32_t* pB = sBb + ((p == 1) ? 128 * SROW : 0);
                if (p != 1) {                 // p==1 reuses p==0's A (hi) fragments
#pragma unroll
                    for (int i = 0; i < NI; i++) {
                        int r = wm * (MT / 2) + i * 16 + (lane >> 2);
                        a[i][0] = pA[r * SROW + k2];
                        a[i][1] = pA[(r + 8) * SROW + k2];
                        a[i][2] = pA[r * SROW + k2 + 4];
                        a[i][3] = pA[(r + 8) * SROW + k2 + 4];
                    }
                }
#pragma unroll
                for (int j = 0; j < 4; j++) {
                    int c = wn * 32 + j * 8 + (lane >> 2);
                    uint32_t b0 = pB[c * SROW + k2];
                    uint32_t b1 = pB[c * SROW + k2 + 4];
#pragma unroll
                    for (int i = 0; i < NI; i++)
                        mma_bf16(acc[i][j], a[i][0], a[i][1], a[i][2], a[i][3], b0, b1);
                }
            }
        }
        // next iteration's first __syncthreads guards sA/sB and raw buffers
    }

    // ---- epilogue (scatter rows via rowidx) ----
#pragma unroll
    for (int i = 0; i < NI; i++) {
        int lr0 = wm * (MT / 2) + i * 16 + (lane >> 2);
#pragma unroll
        for (int j = 0; j < 4; j++) {
            int cc = n0 + wn * 32 + j * 8 + (lane & 3) * 2;
            float bx = 0.f, by = 0.f;
            if (bias) { bx = bias[cc]; by = bias[cc + 1]; }
#pragma unroll
            for (int hrow = 0; hrow < 2; hrow++) {
                int rr = rowidx[lr0 + hrow * 8];
                if (rr < 0) continue;
                float vx = acc[i][j][hrow * 2 + 0] + bx;
                float vy = acc[i][j][hrow * 2 + 1] + by;
                if (do_relu) { vx = fmaxf(vx, 0.f); vy = fmaxf(vy, 0.f); }
                if (addsrc) {
                    const float2 av = *reinterpret_cast<const float2*>(addsrc + (long)rr * ldc + cc);
                    vx += av.x; vy += av.y;
                }
                *reinterpret_cast<float2*>(C + (long)rr * ldc + cc) = make_float2(vx, vy);
            }
        }
    }
}

// ---------------- 64x128x128 SIMT tile for the tiny prep GEMMs ----------------
__device__ __forceinline__ void gemm64(const float* __restrict__ A,
                                       const float* __restrict__ B,
                                       float* __restrict__ C,
                                       int ldc, float alpha, int transB)
{
    __shared__ float As[64][33];
    __shared__ float Bs[32][128];
    int tid = threadIdx.x, tx = tid & 15, ty = tid >> 4;
    float acc[4][8];
#pragma unroll
    for (int i = 0; i < 4; i++)
#pragma unroll
        for (int j = 0; j < 8; j++) acc[i][j] = 0.f;

    for (int kt = 0; kt < 128; kt += 32) {
#pragma unroll
        for (int j = 0; j < 8; j++) {
            int lin = tid + j * 256;
            int lr = lin >> 5, lc = lin & 31;
            As[lr][lc] = A[lr * 128 + kt + lc];
        }
#pragma unroll
        for (int j = 0; j < 16; j++) {
            int lin = tid + j * 256;
            int br = lin >> 7, bc = lin & 127;
            Bs[br][bc] = transB ? B[bc * 128 + kt + br] : B[(kt + br) * 128 + bc];
        }
        __syncthreads();
#pragma unroll
        for (int kk = 0; kk < 32; kk++) {
            float bv[8];
#pragma unroll
            for (int j = 0; j < 8; j++) bv[j] = Bs[kk][tx + 16 * j];
#pragma unroll
            for (int i = 0; i < 4; i++) {
                float av = As[ty * 4 + i][kk];
#pragma unroll
                for (int j = 0; j < 8; j++) acc[i][j] += av * bv[j];
            }
        }
        __syncthreads();
    }
#pragma unroll
    for (int i = 0; i < 4; i++)
#pragma unroll
        for (int j = 0; j < 8; j++)
            C[(ty * 4 + i) * ldc + tx + 16 * j] = acc[i][j] * alpha;
}

// P1: T[r] = rel[r] @ k_w ; S[r] = rel[r] @ v_w   (grid (2,1,16)); also zeroes g_cnt.
__global__ __launch_bounds__(256) void prep1_kernel(const float* __restrict__ rel_w,
                                                    const float* __restrict__ k_w,
                                                    const float* __restrict__ v_w)
{
    if (blockIdx.x == 0 && blockIdx.z == 0 && threadIdx.x < ENTT) g_cnt[threadIdx.x] = 0;
    int z = blockIdx.z, r = z & 7, ph = z >> 3;
    const float* A = rel_w + r * (UU * UU) + blockIdx.x * 64 * UU;
    const float* B = ph ? v_w : k_w;
    float* C = (ph ? g_S : g_T) + r * (UU * UU) + blockIdx.x * 64 * UU;
    gemm64(A, B, C, UU, 1.f, 0);
}

// P2: Bk2[a, r*128+b] = (1/U) sum_e q_w[a,e] T[r][b,e]  (NT) ;  Bv2[r] = S[r] @ fc_w  (NN).
__global__ __launch_bounds__(256) void prep2_kernel(const float* __restrict__ q_w,
                                                    const float* __restrict__ fc_w)
{
    int z = blockIdx.z, r = z & 7, ph = z >> 3;
    if (!ph) {
        const float* A = q_w + blockIdx.x * 64 * UU;
        const float* B = g_T + r * (UU * UU);
        float* C = g_Bk2 + blockIdx.x * 64 * (RR * UU) + r * UU;
        gemm64(A, B, C, RR * UU, 1.f / 128.f, 1);
    } else {
        const float* A = g_S + r * (UU * UU) + blockIdx.x * 64 * UU;
        float* C = g_Bv2 + r * (UU * UU) + blockIdx.x * 64 * UU;
        gemm64(A, fc_w, C, UU, 1.f, 0);
    }
}

// ---------------- entity partition ----------------
__global__ void partition_kernel(const int* __restrict__ pe) {
    int n = blockIdx.x * blockDim.x + threadIdx.x;
    if (n < NN) {
        int e = pe[n];
        int pos = atomicAdd(&g_cnt[e], 1);
        g_lists[e * NN + pos] = n;
    }
}

// ---------------- fused gather / score / softmax / weighted-scatter ----------------
__global__ __launch_bounds__(128) void edge_kernel(const int* __restrict__ adjacency,
                                                   const int* __restrict__ relation)
{
    __shared__ float xs[DD][UU];
    __shared__ float aw[RR][DD];
    __shared__ float scores[DD];
    __shared__ int adjs[DD];
    __shared__ int rels[DD];

    int n = blockIdx.x;
    int tid = threadIdx.x, lane = tid & 31, w = tid >> 5;

    if (tid < DD) {
        adjs[tid] = adjacency[n * DD + tid];
        rels[tid] = relation[n * DD + tid];
    }
    __syncthreads();

#pragma unroll
    for (int i = 0; i < 8; i++) {
        int d = w * 8 + i;
        int idx = adjs[d];
        float4 v = (idx > 0)
            ? reinterpret_cast<const float4*>(g_center + (idx - 1) * UU)[lane]
            : make_float4(0.f, 0.f, 0.f, 0.f);
        reinterpret_cast<float4*>(&xs[d][0])[lane] = v;
    }
    __syncwarp();

    const float* qbase = g_qr + n * (RR * UU);
#pragma unroll
    for (int i = 0; i < 8; i++) {
        int d = w * 8 + i;
        int r = rels[d];
        const float* q = qbase + r * UU;
        float s = 0.f;
#pragma unroll
        for (int k2 = 0; k2 < 4; k2++) {
            int c = lane + 32 * k2;
            s += q[c] * xs[d][c];
        }
#pragma unroll
        for (int off = 16; off > 0; off >>= 1) s += __shfl_xor_sync(0xffffffffu, s, off);
        if (lane == 0) scores[d] = (r == 0) ? -1e9f : s;
    }
    __syncthreads();

    if (w == 0) {
        float v = scores[lane];
        float m = v;
#pragma unroll
        for (int off = 16; off > 0; off >>= 1) m = fmaxf(m, __shfl_xor_sync(0xffffffffu, m, off));
        float e = __expf(v - m);
        float sum = e;
#pragma unroll
        for (int off = 16; off > 0; off >>= 1) sum += __shfl_xor_sync(0xffffffffu, sum, off);
        float a = e / sum;
        int r = rels[lane];
#pragma unroll
        for (int rr = 0; rr < RR; rr++) aw[rr][lane] = (r == rr) ? a : 0.f;
    }
    __syncthreads();

    float acc[RR];
#pragma unroll
    for (int r = 0; r < RR; r++) acc[r] = 0.f;
#pragma unroll
    for (int d = 0; d < DD; d++) {
        float x = xs[d][tid];
#pragma unroll
        for (int r = 0; r < RR; r++) acc[r] += aw[r][d] * x;
    }
    float* sp = g_s + n * (RR * UU) + tid;
#pragma unroll
    for (int r = 0; r < RR; r++) sp[r * UU] = acc[r];
}

// ---------------- launch ----------------
extern "C" void kernel_launch(void* const* d_in, const int* in_sizes, int n_in,
                              void* d_out, int out_size)
{
    const float* node_state = (const float*)d_in[0];
    const int*   adjacency  = (const int*)d_in[1];
    const int*   point_enc  = (const int*)d_in[2];
    const int*   relation   = (const int*)d_in[3];
    const float* pe_w       = (const float*)d_in[4];
    const float* rel_w      = (const float*)d_in[5];
    const float* q_w        = (const float*)d_in[6];
    const float* k_w        = (const float*)d_in[7];
    const float* v_w        = (const float*)d_in[8];
    const float* fc_w       = (const float*)d_in[9];
    const float* fc_b       = (const float*)d_in[10];
    float* out = (float*)d_out;

    float *p_center, *p_qr, *p_s, *p_Bk2, *p_Bv2;
    int *p_cnt, *p_lists;
    cudaGetSymbolAddress((void**)&p_center, g_center);
    cudaGetSymbolAddress((void**)&p_qr,     g_qr);
    cudaGetSymbolAddress((void**)&p_s,      g_s);
    cudaGetSymbolAddress((void**)&p_Bk2,    g_Bk2);
    cudaGetSymbolAddress((void**)&p_Bv2,    g_Bv2);
    cudaGetSymbolAddress((void**)&p_cnt,    g_cnt);
    cudaGetSymbolAddress((void**)&p_lists,  g_lists);

    cudaFuncSetAttribute(mma_gemm<128>, cudaFuncAttributeMaxDynamicSharedMemorySize, SMEM_MMA(128));
    cudaFuncSetAttribute(mma_gemm<64>,  cudaFuncAttributeMaxDynamicSharedMemorySize, SMEM_MMA(64));

    // 1. prep chain (depth 2): T/S then Bk2/Bv2 ; P1 also zeroes g_cnt
    prep1_kernel<<<dim3(2, 1, 16), 256>>>(rel_w, k_w, v_w);
    // 2. entity partition (needs g_cnt zeroed by P1)
    partition_kernel<<<NN / 256, 256>>>(point_enc);
    // 3. prep stage 2
    prep2_kernel<<<dim3(2, 1, 16), 256>>>(q_w, fc_w);

    // 4. center[n] = node_state[n] @ point_enc_w[point_enc[n]]  — gathered pipelined MMA
    mma_gemm<128><<<dim3(32, 1, 8), 256, SMEM_MMA(128)>>>(
        node_state, INPD, pe_w, 128, (long)INPD * UU,
        p_center, 128, INPD,
        p_lists, p_cnt, nullptr, nullptr, 0);

    // 5. qr = center @ Bk2   (N x 1024, K=128)
    mma_gemm<128><<<dim3(128, 8, 1), 256, SMEM_MMA(128)>>>(
        p_center, 128, p_Bk2, 1024, 0L,
        p_qr, 1024, 128,
        nullptr, nullptr, nullptr, nullptr, 0);

    // 6. fused gather / scores / softmax / per-relation weighted sums
    edge_kernel<<<NN, 128>>>(adjacency, relation);

    // 7. out = center + relu(s @ Bv2 + fc_b)   (N x 128, K=1024) — MT=64 for 256 CTAs
    mma_gemm<64><<<dim3(256, 1, 1), 256, SMEM_MMA(64)>>>(
        p_s, 1024, p_Bv2, 128, 0L,
        out, 128, 1024,
        nullptr, nullptr, fc_b, p_center, 1);
}

// round 11
// speedup vs baseline: 2.3349x; 1.2627x over previous
#include <cuda_runtime.h>
#include <cuda_bf16.h>
#include <cstdint>

#define NN  16384
#define DD  32
#define INPD 256
#define UU  128
#define RR  8
#define ENTT 8

// ---------------- scratch (device globals: no allocation allowed) ----------------
__device__ float g_center[NN * UU];                    // (N, U) fp32
__device__ __nv_bfloat16 g_center_h[NN * UU];          // center hi plane
__device__ __nv_bfloat16 g_center_l[NN * UU];          // center lo plane
__device__ float g_qr[NN * RR * UU];                   // (N, R*U) fp32
__device__ __nv_bfloat16 g_sh[NN * RR * UU];           // s hi plane  (N, 1024)
__device__ __nv_bfloat16 g_sl[NN * RR * UU];           // s lo plane
__device__ float g_T[RR * UU * UU];                    // T[r] = rel[r] @ k_w
__device__ float g_S[RR * UU * UU];                    // S[r] = rel[r] @ v_w
__device__ __nv_bfloat16 g_BkTh[RR * UU * UU];         // Bk2^T hi: [1024][128]
__device__ __nv_bfloat16 g_BkTl[RR * UU * UU];         // Bk2^T lo
__device__ __nv_bfloat16 g_BvTh[RR * UU * UU];         // Bv2^T hi: [128][1024]
__device__ __nv_bfloat16 g_BvTl[RR * UU * UU];         // Bv2^T lo
__device__ int   g_cnt[ENTT];
__device__ int   g_lists[ENTT * NN];

// ======================= warp-level bf16 MMA (HMMA path, plain sm_103) =======================
__device__ __forceinline__ void mma_bf16(float* d,
                                         uint32_t a0, uint32_t a1, uint32_t a2, uint32_t a3,
                                         uint32_t b0, uint32_t b1)
{
    asm volatile(
        "mma.sync.aligned.m16n8k16.row.col.f32.bf16.bf16.f32 "
        "{%0,%1,%2,%3}, {%4,%5,%6,%7}, {%8,%9}, {%0,%1,%2,%3};"
        : "+f"(d[0]), "+f"(d[1]), "+f"(d[2]), "+f"(d[3])
        : "r"(a0), "r"(a1), "r"(a2), "r"(a3), "r"(b0), "r"(b1));
}

__device__ __forceinline__ void cp16(uint32_t dst, const void* src, int sz) {
    asm volatile("cp.async.ca.shared.global [%0], [%1], 16, %2;"
                 :: "r"(dst), "l"(src), "r"(sz) : "memory");
}
#define CP_COMMIT() asm volatile("cp.async.commit_group;" ::: "memory")
#define CP_WAIT1()  asm volatile("cp.async.wait_group 1;" ::: "memory")
#define CP_WAIT0()  asm volatile("cp.async.wait_group 0;" ::: "memory")

// XOR swizzle at 16B-chunk granularity: conflict-free for frag loads AND cp.async stores,
// keeps every 16B chunk 16B-aligned (rows are 16 words = 64B of packed bf16x2).
__device__ __forceinline__ int swz(int row, int c) {
    return row * 16 + ((c ^ (row & 3) ^ ((row >> 2) & 1)) << 2);
}

// ======================= pre-split bf16 GEMM (3-stage cp.async pipeline) =======================
// C[MT x 128 tile] = A @ B^T with split-bf16 3-pass; A planes [M][K], BT planes [N][K] bf16.
// Stage words: Ah | Al | Bh | Bl  (each rows*16 words, swizzled).
#define STGW(MT) (2*(MT)*16 + 2*128*16)
#define SMEM_PRE(MT) (3 * STGW(MT) * 4)

template<int MT>
__device__ __forceinline__ void issue_chunk(
    uint32_t sb0, int stage, int kc,
    const __nv_bfloat16* Ah, const __nv_bfloat16* Al,
    const __nv_bfloat16* Bh, const __nv_bfloat16* Bl,
    int K, int m0, int n0, int tid)
{
    uint32_t base = sb0 + stage * STGW(MT) * 4;
#pragma unroll
    for (int it = 0; it < MT / 64; it++) {
        int lin = tid + it * 256;
        int row = lin >> 2, c = lin & 3;
        int wd = swz(row, c);
        long off = (long)(m0 + row) * K + kc * 32 + c * 8;
        cp16(base + wd * 4, Ah + off, 16);
        cp16(base + (MT * 16 + wd) * 4, Al + off, 16);
    }
#pragma unroll
    for (int it = 0; it < 2; it++) {
        int lin = tid + it * 256;
        int row = lin >> 2, c = lin & 3;
        int wd = swz(row, c);
        long off = (long)(n0 + row) * K + kc * 32 + c * 8;
        cp16(base + (2 * MT * 16 + wd) * 4, Bh + off, 16);
        cp16(base + (2 * MT * 16 + 128 * 16 + wd) * 4, Bl + off, 16);
    }
}

template<int MT>
__global__ __launch_bounds__(256, 2) void mma_pre(
    const __nv_bfloat16* __restrict__ Ah, const __nv_bfloat16* __restrict__ Al,
    const __nv_bfloat16* __restrict__ Bh, const __nv_bfloat16* __restrict__ Bl,
    int K,
    float* __restrict__ C, int ldc,
    const float* __restrict__ bias, const float* __restrict__ addsrc, int do_relu)
{
    constexpr int NI = MT / 32;
    extern __shared__ char smem[];
    uint32_t* smw = (uint32_t*)smem;
    uint32_t sb0 = (uint32_t)__cvta_generic_to_shared(smem);

    const int tid  = threadIdx.x;
    const int lane = tid & 31;
    const int w    = tid >> 5;
    const int wm   = w >> 2;
    const int wn   = w & 3;
    const int q    = lane >> 2;
    const int s4   = lane & 3;
    const int m0   = blockIdx.x * MT;
    const int n0   = blockIdx.y * 128;

    float acc[NI][4][4];
#pragma unroll
    for (int i = 0; i < NI; i++)
#pragma unroll
        for (int j = 0; j < 4; j++)
#pragma unroll
            for (int r = 0; r < 4; r++) acc[i][j][r] = 0.f;

    const int nk = K / 32;
    issue_chunk<MT>(sb0, 0, 0, Ah, Al, Bh, Bl, K, m0, n0, tid);
    CP_COMMIT();
    issue_chunk<MT>(sb0, 1, 1, Ah, Al, Bh, Bl, K, m0, n0, tid);
    CP_COMMIT();

    for (int kt = 0; kt < nk; kt++) {
        CP_WAIT1();
        __syncthreads();

        const uint32_t* stg = smw + (kt % 3) * STGW(MT);
        const uint32_t* pAh = stg;
        const uint32_t* pAl = stg + MT * 16;
        const uint32_t* pBh = stg + 2 * MT * 16;
        const uint32_t* pBl = pBh + 128 * 16;

#pragma unroll
        for (int st = 0; st < 2; st++) {
            uint32_t a[NI][4];
#pragma unroll
            for (int p = 0; p < 3; p++) {
                const uint32_t* pA = (p == 2) ? pAl : pAh;
                const uint32_t* pB = (p == 1) ? pBl : pBh;
                if (p != 1) {
#pragma unroll
                    for (int i = 0; i < NI; i++) {
                        int r = wm * (MT / 2) + i * 16 + q;
                        a[i][0] = pA[swz(r, st * 2) + s4];
                        a[i][1] = pA[swz(r + 8, st * 2) + s4];
                        a[i][2] = pA[swz(r, st * 2 + 1) + s4];
                        a[i][3] = pA[swz(r + 8, st * 2 + 1) + s4];
                    }
                }
#pragma unroll
                for (int j = 0; j < 4; j++) {
                    int c = wn * 32 + j * 8 + q;
                    uint32_t b0 = pB[swz(c, st * 2) + s4];
                    uint32_t b1 = pB[swz(c, st * 2 + 1) + s4];
#pragma unroll
                    for (int i = 0; i < NI; i++)
                        mma_bf16(acc[i][j], a[i][0], a[i][1], a[i][2], a[i][3], b0, b1);
                }
            }
        }
        if (kt + 2 < nk)
            issue_chunk<MT>(sb0, (kt + 2) % 3, kt + 2, Ah, Al, Bh, Bl, K, m0, n0, tid);
        CP_COMMIT();
    }

    // ---- epilogue ----
#pragma unroll
    for (int i = 0; i < NI; i++) {
        int r0 = m0 + wm * (MT / 2) + i * 16 + q;
#pragma unroll
        for (int j = 0; j < 4; j++) {
            int cc = n0 + wn * 32 + j * 8 + s4 * 2;
            float bx = 0.f, by = 0.f;
            if (bias) { bx = bias[cc]; by = bias[cc + 1]; }
#pragma unroll
            for (int hrow = 0; hrow < 2; hrow++) {
                int rr = r0 + hrow * 8;
                float vx = acc[i][j][hrow * 2 + 0] + bx;
                float vy = acc[i][j][hrow * 2 + 1] + by;
                if (do_relu) { vx = fmaxf(vx, 0.f); vy = fmaxf(vy, 0.f); }
                if (addsrc) {
                    const float2 av = *reinterpret_cast<const float2*>(addsrc + (long)rr * ldc + cc);
                    vx += av.x; vy += av.y;
                }
                *reinterpret_cast<float2*>(C + (long)rr * ldc + cc) = make_float2(vx, vy);
            }
        }
    }
}

// ======================= fp32-input pipelined MMA (center only: gather + split) ==============
#define SROW 17
#define SMEM_MMA (512 + 128*256 + 32768 + 2*128*SROW*4 + 2*128*SROW*4)

__global__ __launch_bounds__(256) void mma_gemm_f32(
    const float* __restrict__ A, int lda,
    const float* __restrict__ B, int ldb, long sBz,
    float* __restrict__ C, int ldc, int K,
    const int* __restrict__ rowlists, const int* __restrict__ cnts,
    __nv_bfloat16* __restrict__ Ch, __nv_bfloat16* __restrict__ Cl)
{
    constexpr int MT = 128;
    constexpr int NI = 4;
    extern __shared__ char smem[];
    int*      rowidx = (int*)smem;
    float*    rawA   = (float*)(smem + 512);
    float*    rawB   = (float*)(smem + 512 + MT * 256);
    uint32_t* sAb    = (uint32_t*)(smem + 512 + MT * 256 + 32768);
    uint32_t* sBb    = sAb + 2 * MT * SROW;

    const int tid  = threadIdx.x;
    const int lane = tid & 31;
    const int w    = tid >> 5;
    const int wm   = w >> 2;
    const int wn   = w & 3;
    const int m0   = blockIdx.x * MT;
    const int n0   = blockIdx.y * 128;
    const int z    = blockIdx.z;

    int rows = cnts[z];
    if (m0 >= rows) return;
    const int* rl = rowlists + z * NN;
    B += z * sBz;

    if (tid < MT) {
        int g = m0 + tid;
        rowidx[tid] = (g < rows) ? rl[g] : -1;
    }
    __syncthreads();

    float acc[NI][4][4];
#pragma unroll
    for (int i = 0; i < NI; i++)
#pragma unroll
        for (int j = 0; j < 4; j++)
#pragma unroll
            for (int r = 0; r < 4; r++) acc[i][j][r] = 0.f;

    const int nk = K / 32;
    {
#pragma unroll
        for (int it = 0; it < NI; it++) {
            int lin = tid + it * 256;
            int row = lin >> 3, f4 = lin & 7;
            int ar = rowidx[row];
            const float* src = (ar >= 0) ? (A + (long)ar * lda + f4 * 4) : A;
            cp16((uint32_t)__cvta_generic_to_shared(rawA + row * 32 + f4 * 4), src,
                 (ar >= 0) ? 16 : 0);
        }
#pragma unroll
        for (int it = 0; it < 4; it++) {
            int lin = tid + it * 256;
            int kk = lin >> 5, n4 = (lin & 31) * 4;
            cp16((uint32_t)__cvta_generic_to_shared(rawB + kk * 128 + n4),
                 B + (long)kk * ldb + n0 + n4, 16);
        }
        CP_COMMIT();
    }

    for (int kt = 0; kt < nk; kt++) {
        const int cur = kt & 1;
        if (kt + 1 < nk) {
            const int nxt = cur ^ 1;
            const int k0 = (kt + 1) * 32;
#pragma unroll
            for (int it = 0; it < NI; it++) {
                int lin = tid + it * 256;
                int row = lin >> 3, f4 = lin & 7;
                int ar = rowidx[row];
                const float* src = (ar >= 0) ? (A + (long)ar * lda + k0 + f4 * 4) : A;
                cp16((uint32_t)__cvta_generic_to_shared(rawA + nxt * MT * 32 + row * 32 + f4 * 4),
                     src, (ar >= 0) ? 16 : 0);
            }
#pragma unroll
            for (int it = 0; it < 4; it++) {
                int lin = tid + it * 256;
                int kk = lin >> 5, n4 = (lin & 31) * 4;
                cp16((uint32_t)__cvta_generic_to_shared(rawB + nxt * 4096 + kk * 128 + n4),
                     B + (long)(k0 + kk) * ldb + n0 + n4, 16);
            }
            CP_COMMIT();
            CP_WAIT1();
        } else {
            CP_WAIT0();
        }
        __syncthreads();

        const float* rA = rawA + cur * MT * 32;
#pragma unroll
        for (int it = 0; it < NI; it++) {
            int lin = tid + it * 256;
            int row = lin >> 3, f4 = lin & 7;
            float4 v = *reinterpret_cast<const float4*>(rA + row * 32 + f4 * 4);
            __nv_bfloat16 h0 = __float2bfloat16(v.x), h1 = __float2bfloat16(v.y);
            __nv_bfloat16 h2 = __float2bfloat16(v.z), h3 = __float2bfloat16(v.w);
            __nv_bfloat16 l0 = __float2bfloat16(v.x - __bfloat162float(h0));
            __nv_bfloat16 l1 = __float2bfloat16(v.y - __bfloat162float(h1));
            __nv_bfloat16 l2 = __float2bfloat16(v.z - __bfloat162float(h2));
            __nv_bfloat16 l3 = __float2bfloat16(v.w - __bfloat162float(h3));
            int idx = row * SROW + f4 * 2;
            sAb[idx]                 = ((uint32_t)__bfloat16_as_ushort(h1) << 16) | __bfloat16_as_ushort(h0);
            sAb[idx + 1]             = ((uint32_t)__bfloat16_as_ushort(h3) << 16) | __bfloat16_as_ushort(h2);
            sAb[MT * SROW + idx]     = ((uint32_t)__bfloat16_as_ushort(l1) << 16) | __bfloat16_as_ushort(l0);
            sAb[MT * SROW + idx + 1] = ((uint32_t)__bfloat16_as_ushort(l3) << 16) | __bfloat16_as_ushort(l2);
        }
        const float* rB = rawB + cur * 4096;
#pragma unroll
        for (int it = 0; it < 4; it++) {
            int lin = tid + it * 256;
            int kk = lin >> 5, n4 = (lin & 31) * 4;
            float4 v = *reinterpret_cast<const float4*>(rB + kk * 128 + n4);
            float vv[4] = {v.x, v.y, v.z, v.w};
            __nv_bfloat16* pH = reinterpret_cast<__nv_bfloat16*>(sBb);
            __nv_bfloat16* pL = reinterpret_cast<__nv_bfloat16*>(sBb + 128 * SROW);
#pragma unroll
            for (int j = 0; j < 4; j++) {
                __nv_bfloat16 h = __float2bfloat16(vv[j]);
                __nv_bfloat16 l = __float2bfloat16(vv[j] - __bfloat162float(h));
                int bidx = (n4 + j) * (2 * SROW) + kk;
                pH[bidx] = h;
                pL[bidx] = l;
            }
        }
        __syncthreads();

#pragma unroll
        for (int st = 0; st < 2; st++) {
            int k2 = st * 8 + (lane & 3);
            uint32_t a[NI][4];
#pragma unroll
            for (int p = 0; p < 3; p++) {
                const uint32_t* pA = sAb + ((p == 2) ? MT * SROW : 0);
                const uint32_t* pB = sBb + ((p == 1) ? 128 * SROW : 0);
                if (p != 1) {
#pragma unroll
                    for (int i = 0; i < NI; i++) {
                        int r = wm * (MT / 2) + i * 16 + (lane >> 2);
                        a[i][0] = pA[r * SROW + k2];
                        a[i][1] = pA[(r + 8) * SROW + k2];
                        a[i][2] = pA[r * SROW + k2 + 4];
                        a[i][3] = pA[(r + 8) * SROW + k2 + 4];
                    }
                }
#pragma unroll
                for (int j = 0; j < 4; j++) {
                    int c = wn * 32 + j * 8 + (lane >> 2);
                    uint32_t b0 = pB[c * SROW + k2];
                    uint32_t b1 = pB[c * SROW + k2 + 4];
#pragma unroll
                    for (int i = 0; i < NI; i++)
                        mma_bf16(acc[i][j], a[i][0], a[i][1], a[i][2], a[i][3], b0, b1);
                }
            }
        }
    }

    // epilogue: fp32 C + bf16 hi/lo planes (scatter via rowidx)
#pragma unroll
    for (int i = 0; i < NI; i++) {
        int lr0 = wm * (MT / 2) + i * 16 + (lane >> 2);
#pragma unroll
        for (int j = 0; j < 4; j++) {
            int cc = n0 + wn * 32 + j * 8 + (lane & 3) * 2;
#pragma unroll
            for (int hrow = 0; hrow < 2; hrow++) {
                int rr = rowidx[lr0 + hrow * 8];
                if (rr < 0) continue;
                float vx = acc[i][j][hrow * 2 + 0];
                float vy = acc[i][j][hrow * 2 + 1];
                *reinterpret_cast<float2*>(C + (long)rr * ldc + cc) = make_float2(vx, vy);
                __nv_bfloat16 hx = __float2bfloat16(vx), hy = __float2bfloat16(vy);
                __nv_bfloat16 lx = __float2bfloat16(vx - __bfloat162float(hx));
                __nv_bfloat16 ly = __float2bfloat16(vy - __bfloat162float(hy));
                uint32_t ph = ((uint32_t)__bfloat16_as_ushort(hy) << 16) | __bfloat16_as_ushort(hx);
                uint32_t pl = ((uint32_t)__bfloat16_as_ushort(ly) << 16) | __bfloat16_as_ushort(lx);
                reinterpret_cast<uint32_t*>(Ch)[((long)rr * ldc + cc) >> 1] = ph;
                reinterpret_cast<uint32_t*>(Cl)[((long)rr * ldc + cc) >> 1] = pl;
            }
        }
    }
}

// ---------------- 64x128x128 SIMT tile for the tiny prep GEMMs ----------------
// If Cf32: write fp32. Else: write transposed bf16 hi/lo planes oh/ol:
// oh[(colbase+col)*o_ld + rowbase+row] = hi(alpha*acc).
__device__ __forceinline__ void gemm64(const float* __restrict__ A,
                                       const float* __restrict__ B,
                                       float* __restrict__ Cf32, int ldc,
                                       float alpha, int transB,
                                       __nv_bfloat16* oh, __nv_bfloat16* ol,
                                       int o_ld, int rowbase, int colbase)
{
    __shared__ float As[64][33];
    __shared__ float Bs[32][128];
    int tid = threadIdx.x, tx = tid & 15, ty = tid >> 4;
    float acc[4][8];
#pragma unroll
    for (int i = 0; i < 4; i++)
#pragma unroll
        for (int j = 0; j < 8; j++) acc[i][j] = 0.f;

    for (int kt = 0; kt < 128; kt += 32) {
#pragma unroll
        for (int j = 0; j < 8; j++) {
            int lin = tid + j * 256;
            int lr = lin >> 5, lc = lin & 31;
            As[lr][lc] = A[lr * 128 + kt + lc];
        }
#pragma unroll
        for (int j = 0; j < 16; j++) {
            int lin = tid + j * 256;
            int br = lin >> 7, bc = lin & 127;
            Bs[br][bc] = transB ? B[bc * 128 + kt + br] : B[(kt + br) * 128 + bc];
        }
        __syncthreads();
#pragma unroll
        for (int kk = 0; kk < 32; kk++) {
            float bv[8];
#pragma unroll
            for (int j = 0; j < 8; j++) bv[j] = Bs[kk][tx + 16 * j];
#pragma unroll
            for (int i = 0; i < 4; i++) {
                float av = As[ty * 4 + i][kk];
#pragma unroll
                for (int j = 0; j < 8; j++) acc[i][j] += av * bv[j];
            }
        }
        __syncthreads();
    }
    if (Cf32) {
#pragma unroll
        for (int i = 0; i < 4; i++)
#pragma unroll
            for (int j = 0; j < 8; j++)
                Cf32[(ty * 4 + i) * ldc + tx + 16 * j] = acc[i][j] * alpha;
    } else {
#pragma unroll
        for (int i = 0; i < 4; i++) {
            int gr = rowbase + ty * 4 + i;
#pragma unroll
            for (int j = 0; j < 8; j++) {
                int gc = colbase + tx + 16 * j;
                float v = acc[i][j] * alpha;
                __nv_bfloat16 h = __float2bfloat16(v);
                oh[(long)gc * o_ld + gr] = h;
                ol[(long)gc * o_ld + gr] = __float2bfloat16(v - __bfloat162float(h));
            }
        }
    }
}

// P1: T[r] = rel[r] @ k_w ; S[r] = rel[r] @ v_w   (grid (2,1,16)); also zeroes g_cnt.
__global__ __launch_bounds__(256) void prep1_kernel(const float* __restrict__ rel_w,
                                                    const float* __restrict__ k_w,
                                                    const float* __restrict__ v_w)
{
    if (blockIdx.x == 0 && blockIdx.z == 0 && threadIdx.x < ENTT) g_cnt[threadIdx.x] = 0;
    int z = blockIdx.z, r = z & 7, ph = z >> 3;
    const float* A = rel_w + r * (UU * UU) + blockIdx.x * 64 * UU;
    const float* B = ph ? v_w : k_w;
    float* C = (ph ? g_S : g_T) + r * (UU * UU) + blockIdx.x * 64 * UU;
    gemm64(A, B, C, UU, 1.f, 0, nullptr, nullptr, 0, 0, 0);
}

// P2 -> transposed bf16 planes:
//   BkT[c=r*128+b][a] = (1/U) sum_e q_w[a,e] T[r][b,e]   (o_ld=128)
//   BvT[c][k=r*128+i] = (S[r] @ fc_w)[i][c]              (o_ld=1024)
__global__ __launch_bounds__(256) void prep2_kernel(const float* __restrict__ q_w,
                                                    const float* __restrict__ fc_w)
{
    int z = blockIdx.z, r = z & 7, ph = z >> 3;
    if (!ph) {
        const float* A = q_w + blockIdx.x * 64 * UU;
        const float* B = g_T + r * (UU * UU);
        gemm64(A, B, nullptr, 0, 1.f / 128.f, 1,
               g_BkTh, g_BkTl, 128, blockIdx.x * 64, r * UU);
    } else {
        const float* A = g_S + r * (UU * UU) + blockIdx.x * 64 * UU;
        gemm64(A, fc_w, nullptr, 0, 1.f, 0,
               g_BvTh, g_BvTl, 1024, r * UU + blockIdx.x * 64, 0);
    }
}

// ---------------- entity partition ----------------
__global__ void partition_kernel(const int* __restrict__ pe) {
    int n = blockIdx.x * blockDim.x + threadIdx.x;
    if (n < NN) {
        int e = pe[n];
        int pos = atomicAdd(&g_cnt[e], 1);
        g_lists[e * NN + pos] = n;
    }
}

// ---------------- fused gather / score / softmax / weighted-scatter ----------------
__global__ __launch_bounds__(128) void edge_kernel(const int* __restrict__ adjacency,
                                                   const int* __restrict__ relation)
{
    __shared__ float xs[DD][UU];
    __shared__ float aw[RR][DD];
    __shared__ float scores[DD];
    __shared__ int adjs[DD];
    __shared__ int rels[DD];

    int n = blockIdx.x;
    int tid = threadIdx.x, lane = tid & 31, w = tid >> 5;

    if (tid < DD) {
        adjs[tid] = adjacency[n * DD + tid];
        rels[tid] = relation[n * DD + tid];
    }
    __syncthreads();

#pragma unroll
    for (int i = 0; i < 8; i++) {
        int d = w * 8 + i;
        int idx = adjs[d];
        float4 v = (idx > 0)
            ? reinterpret_cast<const float4*>(g_center + (idx - 1) * UU)[lane]
            : make_float4(0.f, 0.f, 0.f, 0.f);
        reinterpret_cast<float4*>(&xs[d][0])[lane] = v;
    }
    __syncwarp();

    const float* qbase = g_qr + n * (RR * UU);
#pragma unroll
    for (int i = 0; i < 8; i++) {
        int d = w * 8 + i;
        int r = rels[d];
        const float* q = qbase + r * UU;
        float s = 0.f;
#pragma unroll
        for (int k2 = 0; k2 < 4; k2++) {
            int c = lane + 32 * k2;
            s += q[c] * xs[d][c];
        }
#pragma unroll
        for (int off = 16; off > 0; off >>= 1) s += __shfl_xor_sync(0xffffffffu, s, off);
        if (lane == 0) scores[d] = (r == 0) ? -1e9f : s;
    }
    __syncthreads();

    if (w == 0) {
        float v = scores[lane];
        float m = v;
#pragma unroll
        for (int off = 16; off > 0; off >>= 1) m = fmaxf(m, __shfl_xor_sync(0xffffffffu, m, off));
        float e = __expf(v - m);
        float sum = e;
#pragma unroll
        for (int off = 16; off > 0; off >>= 1) sum += __shfl_xor_sync(0xffffffffu, sum, off);
        float a = e / sum;
        int r = rels[lane];
#pragma unroll
        for (int rr = 0; rr < RR; rr++) aw[rr][lane] = (r == rr) ? a : 0.f;
    }
    __syncthreads();

    float acc[RR];
#pragma unroll
    for (int r = 0; r < RR; r++) acc[r] = 0.f;
#pragma unroll
    for (int d = 0; d < DD; d++) {
        float x = xs[d][tid];
#pragma unroll
        for (int r = 0; r < RR; r++) acc[r] += aw[r][d] * x;
    }
    __nv_bfloat16* sph = g_sh + (long)n * (RR * UU) + tid;
    __nv_bfloat16* spl = g_sl + (long)n * (RR * UU) + tid;
#pragma unroll
    for (int r = 0; r < RR; r++) {
        float v = acc[r];
        __nv_bfloat16 h = __float2bfloat16(v);
        sph[r * UU] = h;
        spl[r * UU] = __float2bfloat16(v - __bfloat162float(h));
    }
}

// ---------------- launch ----------------
extern "C" void kernel_launch(void* const* d_in, const int* in_sizes, int n_in,
                              void* d_out, int out_size)
{
    const float* node_state = (const float*)d_in[0];
    const int*   adjacency  = (const int*)d_in[1];
    const int*   point_enc  = (const int*)d_in[2];
    const int*   relation   = (const int*)d_in[3];
    const float* pe_w       = (const float*)d_in[4];
    const float* rel_w      = (const float*)d_in[5];
    const float* q_w        = (const float*)d_in[6];
    const float* k_w        = (const float*)d_in[7];
    const float* v_w        = (const float*)d_in[8];
    const float* fc_w       = (const float*)d_in[9];
    const float* fc_b       = (const float*)d_in[10];
    float* out = (float*)d_out;

    float *p_center, *p_qr;
    __nv_bfloat16 *p_ch, *p_cl, *p_sh, *p_sl, *p_bkh, *p_bkl, *p_bvh, *p_bvl;
    int *p_cnt, *p_lists;
    cudaGetSymbolAddress((void**)&p_center, g_center);
    cudaGetSymbolAddress((void**)&p_qr,     g_qr);
    cudaGetSymbolAddress((void**)&p_ch,     g_center_h);
    cudaGetSymbolAddress((void**)&p_cl,     g_center_l);
    cudaGetSymbolAddress((void**)&p_sh,     g_sh);
    cudaGetSymbolAddress((void**)&p_sl,     g_sl);
    cudaGetSymbolAddress((void**)&p_bkh,    g_BkTh);
    cudaGetSymbolAddress((void**)&p_bkl,    g_BkTl);
    cudaGetSymbolAddress((void**)&p_bvh,    g_BvTh);
    cudaGetSymbolAddress((void**)&p_bvl,    g_BvTl);
    cudaGetSymbolAddress((void**)&p_cnt,    g_cnt);
    cudaGetSymbolAddress((void**)&p_lists,  g_lists);

    cudaFuncSetAttribute(mma_gemm_f32, cudaFuncAttributeMaxDynamicSharedMemorySize, SMEM_MMA);
    cudaFuncSetAttribute(mma_pre<128>, cudaFuncAttributeMaxDynamicSharedMemorySize, SMEM_PRE(128));
    cudaFuncSetAttribute(mma_pre<64>,  cudaFuncAttributeMaxDynamicSharedMemorySize, SMEM_PRE(64));

    // 1. prep chain (depth 2): T/S then BkT/BvT planes ; P1 also zeroes g_cnt
    prep1_kernel<<<dim3(2, 1, 16), 256>>>(rel_w, k_w, v_w);
    // 2. entity partition (needs g_cnt zeroed by P1)
    partition_kernel<<<NN / 256, 256>>>(point_enc);
    // 3. prep stage 2 -> pre-split transposed planes
    prep2_kernel<<<dim3(2, 1, 16), 256>>>(q_w, fc_w);

    // 4. center = gathered GEMM; emits fp32 + bf16 hi/lo planes
    mma_gemm_f32<<<dim3(32, 1, 8), 256, SMEM_MMA>>>(
        node_state, INPD, pe_w, 128, (long)INPD * UU,
        p_center, 128, INPD,
        p_lists, p_cnt, p_ch, p_cl);

    // 5. qr = center @ Bk2  (pre-split planes, 3-stage pipeline)
    mma_pre<128><<<dim3(128, 8), 256, SMEM_PRE(128)>>>(
        p_ch, p_cl, p_bkh, p_bkl, 128,
        p_qr, 1024, nullptr, nullptr, 0);

    // 6. fused gather / scores / softmax / per-relation weighted sums -> s hi/lo planes
    edge_kernel<<<NN, 128>>>(adjacency, relation);

    // 7. out = center + relu(s @ Bv2 + fc_b)  (pre-split planes, MT=64, 256 CTAs)
    mma_pre<64><<<dim3(256, 1), 256, SMEM_PRE(64)>>>(
        p_sh, p_sl, p_bvh, p_bvl, 1024,
        out, 128, fc_b, p_center, 1);
}